// round 15
// baseline (speedup 1.0000x reference)
#include <cuda_runtime.h>
#include <cuda_bf16.h>
#include <stdint.h>
#include <math.h>

#define NATOMS 100000
#define NEDGES 1600000
#define NB 128
#define NRBF 32
#define CUTOFF_F 10.0f
#define PI_F 3.14159265358979f
#define LOG2_F 0.69314718055994531f

// ---------------- scratch (static __device__, no allocations) ----------------
__device__ int   g_cnt;
__device__ int   g_ci[NEDGES];
__device__ int   g_cj[NEDGES];
__device__ float g_rc[NEDGES];
__device__ float g_F[(size_t)NEDGES * NRBF];
__device__ float g_x[(size_t)NATOMS * NB];
__device__ float g_xf[(size_t)NATOMS * NB];
__device__ float g_agg[(size_t)NATOMS * NB];

// ---------------- math helpers ----------------
__device__ __forceinline__ float sspf(float v) {
    float ex = __expf(-fabsf(v));
    return fmaxf(v, 0.0f) + __logf(1.0f + ex) - LOG2_F;
}

__device__ __forceinline__ float siluf(float v) {
    return v * (1.0f / (1.0f + __expf(-v)));
}

__device__ __forceinline__ void red_add_v2(float* p, float a, float b) {
    asm volatile("red.global.add.v2.f32 [%0], {%1,%2};"
                 :: "l"(p), "f"(a), "f"(b) : "memory");
}

// HMMA bf16: D(f32) += A(16x16 bf16) * B(16x8 bf16)   [layout validated R5/R6]
__device__ __forceinline__ void mma_bf16(float* c, const uint32_t* a, const uint32_t* b) {
    asm volatile(
        "mma.sync.aligned.m16n8k16.row.col.f32.bf16.bf16.f32 "
        "{%0,%1,%2,%3}, {%4,%5,%6,%7}, {%8,%9}, {%0,%1,%2,%3};"
        : "+f"(c[0]), "+f"(c[1]), "+f"(c[2]), "+f"(c[3])
        : "r"(a[0]), "r"(a[1]), "r"(a[2]), "r"(a[3]), "r"(b[0]), "r"(b[1]));
}

__device__ __forceinline__ void bf16_split(float v, __nv_bfloat16& hi, __nv_bfloat16& lo) {
    hi = __float2bfloat16(v);
    lo = __float2bfloat16(v - __bfloat162float(hi));
}

// ---------------- smem byte offsets for edge kernel ----------------
#define SM_B1    0
#define SM_B2    512
#define SM_RC    1024
#define SM_II    1536
#define SM_JJ    2048
#define SM_FHI   2560
#define SM_FLO   12800
#define SM_W1HI  23040
#define SM_W1LO  33280
#define SM_HHI   43520
#define SM_HLO   78336
#define SM_WHI   113152
#define SM_WLO   147968
#define EDGE_SMEM_BYTES 182784

// ---------------- smem byte offsets for node gemm kernel ----------------
#define NSM_B    0
#define NSM_INHI 512
#define NSM_INLO 35328
#define NSM_WHI  70144
#define NSM_WLO  104960
#define NODE_SMEM_BYTES 139776

// ---------------- smem byte offsets for fused f2out kernel ----------------
#define N2_B1    0
#define N2_B2    512
#define N2_INHI  1024
#define N2_INLO  35840
#define N2_W1HI  70656
#define N2_W1LO  105472
#define N2_W2HI  140288
#define N2_W2LO  175104
#define NODE2_SMEM_BYTES 209920

// ---------------- prep kernels ----------------
__global__ void prep_zero() {
    if (threadIdx.x == 0) g_cnt = 0;
}

__global__ void edge_compact(const float* __restrict__ pos,
                             const int* __restrict__ idx_i,
                             const int* __restrict__ idx_j,
                             const int* __restrict__ edge_attr,
                             const float* __restrict__ edge_emb, int E) {
    int e = blockIdx.x * blockDim.x + threadIdx.x;
    int lane = threadIdx.x & 31;
    bool active = false;
    int a = 0, b = 0;
    float dd = 0.f;
    if (e < E) {
        a = idx_i[e]; b = idx_j[e];
        float dx = pos[a * 3 + 0] - pos[b * 3 + 0];
        float dy = pos[a * 3 + 1] - pos[b * 3 + 1];
        float dz = pos[a * 3 + 2] - pos[b * 3 + 2];
        dd = sqrtf(dx * dx + dy * dy + dz * dz);
        active = (dd < CUTOFF_F);
    }
    unsigned mask = __ballot_sync(0xffffffffu, active);
    if (!active) return;
    int leader = __ffs(mask) - 1;
    int rank = __popc(mask & ((1u << lane) - 1));
    int base = 0;
    if (lane == leader) base = atomicAdd(&g_cnt, __popc(mask));
    base = __shfl_sync(mask, base, leader);
    int p = base + rank;

    g_ci[p] = a;
    g_cj[p] = b;
    g_rc[p] = 0.5f * (__cosf(dd * (PI_F / CUTOFF_F)) + 1.0f);

    const float width = CUTOFF_F / 31.0f;
    const float coeff = -0.5f / (width * width);
    const float* emb = edge_emb + edge_attr[e] * NRBF;
    float4* dst = (float4*)(g_F + (size_t)p * NRBF);
#pragma unroll
    for (int j = 0; j < 8; j++) {
        float4 v;
        float u0 = dd - (float)(4 * j + 0) * width;
        float u1 = dd - (float)(4 * j + 1) * width;
        float u2 = dd - (float)(4 * j + 2) * width;
        float u3 = dd - (float)(4 * j + 3) * width;
        v.x = __expf(coeff * u0 * u0) + emb[4 * j + 0];
        v.y = __expf(coeff * u1 * u1) + emb[4 * j + 1];
        v.z = __expf(coeff * u2 * u2) + emb[4 * j + 2];
        v.w = __expf(coeff * u3 * u3) + emb[4 * j + 3];
        dst[j] = v;
    }
}

__global__ void embed_zero(const int* __restrict__ z, const int* __restrict__ z_res,
                           const float* __restrict__ ele_emb, const float* __restrict__ res_emb,
                           float* __restrict__ x, float* __restrict__ agg,
                           float* __restrict__ outbuf, int N, int out_n) {
    int t = blockIdx.x * blockDim.x + threadIdx.x;
    if (t < out_n) outbuf[t] = 0.f;
    if (t >= N * NB) return;
    int n = t >> 7, c = t & 127;
    agg[t] = 0.f;
    x[t] = ele_emb[z[n] * NB + c] + res_emb[z_res[n] * NB + c];
}

// ---------------- persistent HMMA node GEMM (1024 thr, R10-proven) ----------------
// PRE: 0=none, 2=L2-normalize then silu
template <int PRE>
__global__ __launch_bounds__(1024, 1) void hmma_node_gemm(
    const float* __restrict__ in, const float* __restrict__ W,
    const float* __restrict__ bias,
    float* __restrict__ out, int M, int ntiles)
{
    extern __shared__ char smch[];
    float* sB = (float*)(smch + NSM_B);

    const int t = threadIdx.x;
    const int wid = t >> 5;
    const int lane = t & 31;
    const int q = lane & 3;
    const int lr = lane >> 2;

    if (t < 128) sB[t] = bias ? bias[t] : 0.f;
#pragma unroll
    for (int i = 0; i < 4; i++) {
        int idx4 = i * 1024 + t;
        int k = idx4 >> 5;
        int n0 = (idx4 & 31) * 4;
        float4 w = ((const float4*)W)[idx4];
        float vs[4] = { w.x, w.y, w.z, w.w };
#pragma unroll
        for (int d = 0; d < 4; d++) {
            __nv_bfloat16 hi, lo;
            bf16_split(vs[d], hi, lo);
            size_t off = ((size_t)(n0 + d) * 136 + k) * 2;
            *(__nv_bfloat16*)(smch + NSM_WHI + off) = hi;
            *(__nv_bfloat16*)(smch + NSM_WLO + off) = lo;
        }
    }
    __syncthreads();

    const int mg = wid & 3;   // 4 row groups of 32
    const int ng = wid >> 2;  // 8 col groups of 16

    for (int tile = blockIdx.x; tile < ntiles; tile += gridDim.x) {
        const int m0 = tile * 128;

        // stage input: thread t -> row t>>3, cols (t&7)*16..+16
        {
            int r = t >> 3, cq = (t & 7) * 16;
            const float4* src = (const float4*)(in + (size_t)(m0 + r) * NB + cq);
            bool ok = (m0 + r < M);
            float4 fv[4];
#pragma unroll
            for (int j = 0; j < 4; j++)
                fv[j] = ok ? src[j] : make_float4(0.f, 0.f, 0.f, 0.f);
            float scale = 1.0f;
            if (PRE == 2) {
                float ss = 0.f;
#pragma unroll
                for (int j = 0; j < 4; j++)
                    ss += fv[j].x * fv[j].x + fv[j].y * fv[j].y + fv[j].z * fv[j].z + fv[j].w * fv[j].w;
                ss += __shfl_xor_sync(0xffffffffu, ss, 1);
                ss += __shfl_xor_sync(0xffffffffu, ss, 2);
                ss += __shfl_xor_sync(0xffffffffu, ss, 4);
                scale = 1.0f / fmaxf(sqrtf(ss), 1e-12f);
            }
#pragma unroll
            for (int j = 0; j < 4; j++) {
                float4 f = fv[j];
                if (PRE == 2) {
                    f.x = siluf(f.x * scale); f.y = siluf(f.y * scale);
                    f.z = siluf(f.z * scale); f.w = siluf(f.w * scale);
                }
                __nv_bfloat162 h0, h1, l0, l1;
                bf16_split(f.x, h0.x, l0.x); bf16_split(f.y, h0.y, l0.y);
                bf16_split(f.z, h1.x, l1.x); bf16_split(f.w, h1.y, l1.y);
                size_t off = ((size_t)r * 136 + cq + j * 4) * 2;
                *(uint2*)(smch + NSM_INHI + off) = make_uint2(*(uint32_t*)&h0, *(uint32_t*)&h1);
                *(uint2*)(smch + NSM_INLO + off) = make_uint2(*(uint32_t*)&l0, *(uint32_t*)&l1);
            }
        }
        __syncthreads();

        float acc[2][2][4];
#pragma unroll
        for (int mt = 0; mt < 2; mt++)
#pragma unroll
            for (int nt = 0; nt < 2; nt++)
#pragma unroll
                for (int v = 0; v < 4; v++) acc[mt][nt][v] = 0.f;

#pragma unroll 2
        for (int ks = 0; ks < 8; ks++) {
            const int k0 = ks * 16;
            uint32_t ahi[2][4], alo[2][4];
#pragma unroll
            for (int mt = 0; mt < 2; mt++) {
                int m = mg * 32 + mt * 16 + lr;
                size_t o0 = ((size_t)m * 136 + k0 + 2 * q) * 2;
                size_t o1 = ((size_t)(m + 8) * 136 + k0 + 2 * q) * 2;
                ahi[mt][0] = *(const uint32_t*)(smch + NSM_INHI + o0);
                ahi[mt][1] = *(const uint32_t*)(smch + NSM_INHI + o1);
                ahi[mt][2] = *(const uint32_t*)(smch + NSM_INHI + o0 + 16);
                ahi[mt][3] = *(const uint32_t*)(smch + NSM_INHI + o1 + 16);
                alo[mt][0] = *(const uint32_t*)(smch + NSM_INLO + o0);
                alo[mt][1] = *(const uint32_t*)(smch + NSM_INLO + o1);
                alo[mt][2] = *(const uint32_t*)(smch + NSM_INLO + o0 + 16);
                alo[mt][3] = *(const uint32_t*)(smch + NSM_INLO + o1 + 16);
            }
#pragma unroll
            for (int nt = 0; nt < 2; nt++) {
                int n = ng * 16 + nt * 8 + lr;
                size_t ob = ((size_t)n * 136 + k0 + 2 * q) * 2;
                uint32_t bhi[2] = { *(const uint32_t*)(smch + NSM_WHI + ob),
                                    *(const uint32_t*)(smch + NSM_WHI + ob + 16) };
                uint32_t blo[2] = { *(const uint32_t*)(smch + NSM_WLO + ob),
                                    *(const uint32_t*)(smch + NSM_WLO + ob + 16) };
#pragma unroll
                for (int mt = 0; mt < 2; mt++) {
                    mma_bf16(acc[mt][nt], ahi[mt], bhi);
                    mma_bf16(acc[mt][nt], ahi[mt], blo);
                    mma_bf16(acc[mt][nt], alo[mt], bhi);
                }
            }
        }

#pragma unroll
        for (int mt = 0; mt < 2; mt++) {
#pragma unroll
            for (int half = 0; half < 2; half++) {
                int rr = mg * 32 + mt * 16 + lr + 8 * half;
                int m = m0 + rr;
                if (m < M) {
                    float* orow = out + (size_t)m * NB;
#pragma unroll
                    for (int nt = 0; nt < 2; nt++) {
                        int c = ng * 16 + nt * 8 + 2 * q;
                        float2 bv = *(const float2*)&sB[c];
                        *(float2*)(orow + c) = make_float2(acc[mt][nt][2 * half] + bv.x,
                                                           acc[mt][nt][2 * half + 1] + bv.y);
                    }
                }
            }
        }
        __syncthreads();
    }
}

// ---------------- fused f2out (1024 thr, R10-proven): x += ssp(agg@W1+b1)@W2+b2 ; zero agg ----------------
__global__ __launch_bounds__(1024, 1) void hmma_f2out(
    const float* __restrict__ agg_in, const float* __restrict__ W1,
    const float* __restrict__ b1, const float* __restrict__ W2,
    const float* __restrict__ b2, float* __restrict__ x,
    float* __restrict__ aggz, int M, int ntiles)
{
    extern __shared__ char smch[];
    float* sB1 = (float*)(smch + N2_B1);
    float* sB2 = (float*)(smch + N2_B2);

    const int t = threadIdx.x;
    const int wid = t >> 5;
    const int lane = t & 31;
    const int q = lane & 3;
    const int lr = lane >> 2;

    if (t < 128) { sB1[t] = b1[t]; sB2[t] = b2[t]; }
#pragma unroll
    for (int i = 0; i < 4; i++) {
        int idx4 = i * 1024 + t;
        int k = idx4 >> 5;
        int n0 = (idx4 & 31) * 4;
        float4 w1 = ((const float4*)W1)[idx4];
        float4 w2 = ((const float4*)W2)[idx4];
        float v1[4] = { w1.x, w1.y, w1.z, w1.w };
        float v2[4] = { w2.x, w2.y, w2.z, w2.w };
#pragma unroll
        for (int d = 0; d < 4; d++) {
            size_t off = ((size_t)(n0 + d) * 136 + k) * 2;
            __nv_bfloat16 hi, lo;
            bf16_split(v1[d], hi, lo);
            *(__nv_bfloat16*)(smch + N2_W1HI + off) = hi;
            *(__nv_bfloat16*)(smch + N2_W1LO + off) = lo;
            bf16_split(v2[d], hi, lo);
            *(__nv_bfloat16*)(smch + N2_W2HI + off) = hi;
            *(__nv_bfloat16*)(smch + N2_W2LO + off) = lo;
        }
    }
    __syncthreads();

    const int mg = wid & 3;
    const int ng = wid >> 2;

    for (int tile = blockIdx.x; tile < ntiles; tile += gridDim.x) {
        const int m0 = tile * 128;

        {
            int r = t >> 3, cq = (t & 7) * 16;
            const float4* src = (const float4*)(agg_in + (size_t)(m0 + r) * NB + cq);
            bool ok = (m0 + r < M);
#pragma unroll
            for (int j = 0; j < 4; j++) {
                float4 f = ok ? src[j] : make_float4(0.f, 0.f, 0.f, 0.f);
                __nv_bfloat162 h0, h1, l0, l1;
                bf16_split(f.x, h0.x, l0.x); bf16_split(f.y, h0.y, l0.y);
                bf16_split(f.z, h1.x, l1.x); bf16_split(f.w, h1.y, l1.y);
                size_t off = ((size_t)r * 136 + cq + j * 4) * 2;
                *(uint2*)(smch + N2_INHI + off) = make_uint2(*(uint32_t*)&h0, *(uint32_t*)&h1);
                *(uint2*)(smch + N2_INLO + off) = make_uint2(*(uint32_t*)&l0, *(uint32_t*)&l1);
            }
        }
        __syncthreads();

        float acc[2][2][4];
#pragma unroll
        for (int mt = 0; mt < 2; mt++)
#pragma unroll
            for (int nt = 0; nt < 2; nt++)
#pragma unroll
                for (int v = 0; v < 4; v++) acc[mt][nt][v] = 0.f;

        // phase 1: C1 = agg @ W1
#pragma unroll 2
        for (int ks = 0; ks < 8; ks++) {
            const int k0 = ks * 16;
            uint32_t ahi[2][4], alo[2][4];
#pragma unroll
            for (int mt = 0; mt < 2; mt++) {
                int m = mg * 32 + mt * 16 + lr;
                size_t o0 = ((size_t)m * 136 + k0 + 2 * q) * 2;
                size_t o1 = ((size_t)(m + 8) * 136 + k0 + 2 * q) * 2;
                ahi[mt][0] = *(const uint32_t*)(smch + N2_INHI + o0);
                ahi[mt][1] = *(const uint32_t*)(smch + N2_INHI + o1);
                ahi[mt][2] = *(const uint32_t*)(smch + N2_INHI + o0 + 16);
                ahi[mt][3] = *(const uint32_t*)(smch + N2_INHI + o1 + 16);
                alo[mt][0] = *(const uint32_t*)(smch + N2_INLO + o0);
                alo[mt][1] = *(const uint32_t*)(smch + N2_INLO + o1);
                alo[mt][2] = *(const uint32_t*)(smch + N2_INLO + o0 + 16);
                alo[mt][3] = *(const uint32_t*)(smch + N2_INLO + o1 + 16);
            }
#pragma unroll
            for (int nt = 0; nt < 2; nt++) {
                int n = ng * 16 + nt * 8 + lr;
                size_t ob = ((size_t)n * 136 + k0 + 2 * q) * 2;
                uint32_t bhi[2] = { *(const uint32_t*)(smch + N2_W1HI + ob),
                                    *(const uint32_t*)(smch + N2_W1HI + ob + 16) };
                uint32_t blo[2] = { *(const uint32_t*)(smch + N2_W1LO + ob),
                                    *(const uint32_t*)(smch + N2_W1LO + ob + 16) };
#pragma unroll
                for (int mt = 0; mt < 2; mt++) {
                    mma_bf16(acc[mt][nt], ahi[mt], bhi);
                    mma_bf16(acc[mt][nt], ahi[mt], blo);
                    mma_bf16(acc[mt][nt], alo[mt], bhi);
                }
            }
        }
        __syncthreads();  // all phase-1 reads of IN done

        // H = ssp(C1 + b1) -> overwrite IN buffers
#pragma unroll
        for (int mt = 0; mt < 2; mt++) {
#pragma unroll
            for (int half = 0; half < 2; half++) {
                int rr = mg * 32 + mt * 16 + lr + 8 * half;
#pragma unroll
                for (int nt = 0; nt < 2; nt++) {
                    int c = ng * 16 + nt * 8 + 2 * q;
                    float2 bv = *(const float2*)&sB1[c];
                    float h0 = sspf(acc[mt][nt][2 * half] + bv.x);
                    float h1 = sspf(acc[mt][nt][2 * half + 1] + bv.y);
                    __nv_bfloat162 hh, ll;
                    bf16_split(h0, hh.x, ll.x);
                    bf16_split(h1, hh.y, ll.y);
                    size_t off = ((size_t)rr * 136 + c) * 2;
                    *(uint32_t*)(smch + N2_INHI + off) = *(uint32_t*)&hh;
                    *(uint32_t*)(smch + N2_INLO + off) = *(uint32_t*)&ll;
                }
            }
        }
        __syncthreads();

        // phase 2: C2 = H @ W2
#pragma unroll
        for (int mt = 0; mt < 2; mt++)
#pragma unroll
            for (int nt = 0; nt < 2; nt++)
#pragma unroll
                for (int v = 0; v < 4; v++) acc[mt][nt][v] = 0.f;

#pragma unroll 2
        for (int ks = 0; ks < 8; ks++) {
            const int k0 = ks * 16;
            uint32_t ahi[2][4], alo[2][4];
#pragma unroll
            for (int mt = 0; mt < 2; mt++) {
                int m = mg * 32 + mt * 16 + lr;
                size_t o0 = ((size_t)m * 136 + k0 + 2 * q) * 2;
                size_t o1 = ((size_t)(m + 8) * 136 + k0 + 2 * q) * 2;
                ahi[mt][0] = *(const uint32_t*)(smch + N2_INHI + o0);
                ahi[mt][1] = *(const uint32_t*)(smch + N2_INHI + o1);
                ahi[mt][2] = *(const uint32_t*)(smch + N2_INHI + o0 + 16);
                ahi[mt][3] = *(const uint32_t*)(smch + N2_INHI + o1 + 16);
                alo[mt][0] = *(const uint32_t*)(smch + N2_INLO + o0);
                alo[mt][1] = *(const uint32_t*)(smch + N2_INLO + o1);
                alo[mt][2] = *(const uint32_t*)(smch + N2_INLO + o0 + 16);
                alo[mt][3] = *(const uint32_t*)(smch + N2_INLO + o1 + 16);
            }
#pragma unroll
            for (int nt = 0; nt < 2; nt++) {
                int n = ng * 16 + nt * 8 + lr;
                size_t ob = ((size_t)n * 136 + k0 + 2 * q) * 2;
                uint32_t bhi[2] = { *(const uint32_t*)(smch + N2_W2HI + ob),
                                    *(const uint32_t*)(smch + N2_W2HI + ob + 16) };
                uint32_t blo[2] = { *(const uint32_t*)(smch + N2_W2LO + ob),
                                    *(const uint32_t*)(smch + N2_W2LO + ob + 16) };
#pragma unroll
                for (int mt = 0; mt < 2; mt++) {
                    mma_bf16(acc[mt][nt], ahi[mt], bhi);
                    mma_bf16(acc[mt][nt], ahi[mt], blo);
                    mma_bf16(acc[mt][nt], alo[mt], bhi);
                }
            }
        }

        // epilogue: x += C2 + b2 ; zero agg
#pragma unroll
        for (int mt = 0; mt < 2; mt++) {
#pragma unroll
            for (int half = 0; half < 2; half++) {
                int rr = mg * 32 + mt * 16 + lr + 8 * half;
                int m = m0 + rr;
                if (m < M) {
                    float* xrow = x + (size_t)m * NB;
                    float* zrow = aggz ? aggz + (size_t)m * NB : 0;
#pragma unroll
                    for (int nt = 0; nt < 2; nt++) {
                        int c = ng * 16 + nt * 8 + 2 * q;
                        float2 bv = *(const float2*)&sB2[c];
                        float2 xv = *(const float2*)(xrow + c);
                        *(float2*)(xrow + c) = make_float2(xv.x + acc[mt][nt][2 * half] + bv.x,
                                                           xv.y + acc[mt][nt][2 * half + 1] + bv.y);
                        if (aggz) *(float2*)(zrow + c) = make_float2(0.f, 0.f);
                    }
                }
            }
        }
        __syncthreads();
    }
}

// ---------------- persistent fused edge kernel (512 thr, exact R9-best) ----------------
__global__ __launch_bounds__(512, 1) void edge_kernel(
    const int* __restrict__ ci, const int* __restrict__ cj,
    const float* __restrict__ W1, const float* __restrict__ b1,
    const float* __restrict__ W2, const float* __restrict__ b2,
    const float* __restrict__ Ff, const float* __restrict__ rcut,
    const float* __restrict__ xf, float* __restrict__ agg,
    const int* __restrict__ cntPtr)
{
    extern __shared__ char smch[];
    float* sB1 = (float*)(smch + SM_B1);
    float* sB2 = (float*)(smch + SM_B2);
    float* sRC = (float*)(smch + SM_RC);
    int*   sII = (int*)(smch + SM_II);
    int*   sJJ = (int*)(smch + SM_JJ);

    const int E = *cntPtr;
    const int ntiles = (E + 127) >> 7;

    const int t = threadIdx.x;
    const int wid = t >> 5;
    const int lane = t & 31;
    const int q = lane & 3;
    const int lr = lane >> 2;

    if (t < 128) { sB1[t] = b1[t]; sB2[t] = b2[t]; }
#pragma unroll
    for (int i = 0; i < 2; i++) {
        int idx4 = i * 512 + t;
        int k = idx4 >> 5;
        int n0 = (idx4 & 31) * 4;
        float4 w = ((const float4*)W1)[idx4];
        float vs[4] = { w.x, w.y, w.z, w.w };
#pragma unroll
        for (int d = 0; d < 4; d++) {
            __nv_bfloat16 hi, lo;
            bf16_split(vs[d], hi, lo);
            size_t off = ((size_t)(n0 + d) * 40 + k) * 2;
            *(__nv_bfloat16*)(smch + SM_W1HI + off) = hi;
            *(__nv_bfloat16*)(smch + SM_W1LO + off) = lo;
        }
    }
#pragma unroll
    for (int i = 0; i < 8; i++) {
        int idx4 = i * 512 + t;
        int k = idx4 >> 5;
        int n0 = (idx4 & 31) * 4;
        float4 w = ((const float4*)W2)[idx4];
        float vs[4] = { w.x, w.y, w.z, w.w };
#pragma unroll
        for (int d = 0; d < 4; d++) {
            __nv_bfloat16 hi, lo;
            bf16_split(vs[d], hi, lo);
            size_t off = ((size_t)(n0 + d) * 136 + k) * 2;
            *(__nv_bfloat16*)(smch + SM_WHI + off) = hi;
            *(__nv_bfloat16*)(smch + SM_WLO + off) = lo;
        }
    }

    const int mg = wid & 3;
    const int ng = wid >> 2;

    for (int tile = blockIdx.x; tile < ntiles; tile += gridDim.x) {
        const int eb = tile * 128;

        {
            int r = t >> 2, kq = (t & 3) * 8;
            float4 f0 = make_float4(0.f, 0.f, 0.f, 0.f);
            float4 f1 = make_float4(0.f, 0.f, 0.f, 0.f);
            if (eb + r < E) {
                const float4* src = (const float4*)(Ff + (size_t)(eb + r) * NRBF + kq);
                f0 = src[0]; f1 = src[1];
            }
            __nv_bfloat162 h0, h1, h2, h3, l0, l1, l2, l3;
            bf16_split(f0.x, h0.x, l0.x); bf16_split(f0.y, h0.y, l0.y);
            bf16_split(f0.z, h1.x, l1.x); bf16_split(f0.w, h1.y, l1.y);
            bf16_split(f1.x, h2.x, l2.x); bf16_split(f1.y, h2.y, l2.y);
            bf16_split(f1.z, h3.x, l3.x); bf16_split(f1.w, h3.y, l3.y);
            size_t off = ((size_t)r * 40 + kq) * 2;
            uint4 uh = make_uint4(*(uint32_t*)&h0, *(uint32_t*)&h1, *(uint32_t*)&h2, *(uint32_t*)&h3);
            uint4 ul = make_uint4(*(uint32_t*)&l0, *(uint32_t*)&l1, *(uint32_t*)&l2, *(uint32_t*)&l3);
            *(uint4*)(smch + SM_FHI + off) = uh;
            *(uint4*)(smch + SM_FLO + off) = ul;
        }
        if (t < 128) {
            int e = eb + t;
            float rcv = 0.f; int iiv = 0, jjv = 0;
            if (e < E) { rcv = rcut[e]; iiv = ci[e]; jjv = cj[e]; }
            sRC[t] = rcv; sII[t] = iiv; sJJ[t] = jjv;
        }
        __syncthreads();

        // ---- phase 1: warp pm=wid&7 rows 16; pn=wid>>3 cols 64
        {
            const int pm = wid & 7, pn = wid >> 3;
            const int m0 = pm * 16, n0 = pn * 64;
            uint32_t ahi[2][4], alo[2][4];
#pragma unroll
            for (int ks = 0; ks < 2; ks++) {
                size_t o0 = ((size_t)(m0 + lr) * 40 + ks * 16 + 2 * q) * 2;
                size_t o1 = o0 + 640;
                ahi[ks][0] = *(const uint32_t*)(smch + SM_FHI + o0);
                ahi[ks][1] = *(const uint32_t*)(smch + SM_FHI + o1);
                ahi[ks][2] = *(const uint32_t*)(smch + SM_FHI + o0 + 16);
                ahi[ks][3] = *(const uint32_t*)(smch + SM_FHI + o1 + 16);
                alo[ks][0] = *(const uint32_t*)(smch + SM_FLO + o0);
                alo[ks][1] = *(const uint32_t*)(smch + SM_FLO + o1);
                alo[ks][2] = *(const uint32_t*)(smch + SM_FLO + o0 + 16);
                alo[ks][3] = *(const uint32_t*)(smch + SM_FLO + o1 + 16);
            }
#pragma unroll
            for (int nt = 0; nt < 8; nt++) {
                int n = n0 + nt * 8 + lr;
                float c[4] = { 0.f, 0.f, 0.f, 0.f };
#pragma unroll
                for (int ks = 0; ks < 2; ks++) {
                    size_t ob = ((size_t)n * 40 + ks * 16 + 2 * q) * 2;
                    uint32_t bh[2] = { *(const uint32_t*)(smch + SM_W1HI + ob),
                                       *(const uint32_t*)(smch + SM_W1HI + ob + 16) };
                    uint32_t bl[2] = { *(const uint32_t*)(smch + SM_W1LO + ob),
                                       *(const uint32_t*)(smch + SM_W1LO + ob + 16) };
                    mma_bf16(c, ahi[ks], bh);
                    mma_bf16(c, ahi[ks], bl);
                    mma_bf16(c, alo[ks], bh);
                }
                int cc = n0 + nt * 8 + 2 * q;
                float2 bv = *(const float2*)&sB1[cc];
                float h00 = sspf(c[0] + bv.x), h01 = sspf(c[1] + bv.y);
                float h10 = sspf(c[2] + bv.x), h11 = sspf(c[3] + bv.y);
                __nv_bfloat162 p0, p1, e0, e1;
                bf16_split(h00, p0.x, e0.x); bf16_split(h01, p0.y, e0.y);
                bf16_split(h10, p1.x, e1.x); bf16_split(h11, p1.y, e1.y);
                size_t oh0 = ((size_t)(m0 + lr) * 136 + cc) * 2;
                size_t oh1 = oh0 + 136 * 8 * 2;
                *(uint32_t*)(smch + SM_HHI + oh0) = *(uint32_t*)&p0;
                *(uint32_t*)(smch + SM_HHI + oh1) = *(uint32_t*)&p1;
                *(uint32_t*)(smch + SM_HLO + oh0) = *(uint32_t*)&e0;
                *(uint32_t*)(smch + SM_HLO + oh1) = *(uint32_t*)&e1;
            }
        }
        __syncthreads();

        // ---- phase 2: mg rows 32, ng cols 32 (R9 tiling)
        {
            float acc[2][4][4];
#pragma unroll
            for (int mt = 0; mt < 2; mt++)
#pragma unroll
                for (int nt = 0; nt < 4; nt++)
#pragma unroll
                    for (int v = 0; v < 4; v++) acc[mt][nt][v] = 0.f;

#pragma unroll 2
            for (int ks = 0; ks < 8; ks++) {
                const int k0 = ks * 16;
                uint32_t ahi[2][4], alo[2][4];
#pragma unroll
                for (int mt = 0; mt < 2; mt++) {
                    int m = mg * 32 + mt * 16 + lr;
                    size_t o0 = ((size_t)m * 136 + k0 + 2 * q) * 2;
                    size_t o1 = ((size_t)(m + 8) * 136 + k0 + 2 * q) * 2;
                    ahi[mt][0] = *(const uint32_t*)(smch + SM_HHI + o0);
                    ahi[mt][1] = *(const uint32_t*)(smch + SM_HHI + o1);
                    ahi[mt][2] = *(const uint32_t*)(smch + SM_HHI + o0 + 16);
                    ahi[mt][3] = *(const uint32_t*)(smch + SM_HHI + o1 + 16);
                    alo[mt][0] = *(const uint32_t*)(smch + SM_HLO + o0);
                    alo[mt][1] = *(const uint32_t*)(smch + SM_HLO + o1);
                    alo[mt][2] = *(const uint32_t*)(smch + SM_HLO + o0 + 16);
                    alo[mt][3] = *(const uint32_t*)(smch + SM_HLO + o1 + 16);
                }
#pragma unroll
                for (int nt = 0; nt < 4; nt++) {
                    int n = ng * 32 + nt * 8 + lr;
                    size_t ob = ((size_t)n * 136 + k0 + 2 * q) * 2;
                    uint32_t bhi[2] = { *(const uint32_t*)(smch + SM_WHI + ob),
                                        *(const uint32_t*)(smch + SM_WHI + ob + 16) };
                    uint32_t blo[2] = { *(const uint32_t*)(smch + SM_WLO + ob),
                                        *(const uint32_t*)(smch + SM_WLO + ob + 16) };
#pragma unroll
                    for (int mt = 0; mt < 2; mt++) {
                        mma_bf16(acc[mt][nt], ahi[mt], bhi);
                        mma_bf16(acc[mt][nt], ahi[mt], blo);
                        mma_bf16(acc[mt][nt], alo[mt], bhi);
                    }
                }
            }

            // ---- epilogue (R9): gather xf, scale, red.v2
#pragma unroll
            for (int mt = 0; mt < 2; mt++) {
#pragma unroll
                for (int half = 0; half < 2; half++) {
                    int r = mg * 32 + mt * 16 + lr + 8 * half;
                    float rc = sRC[r];
                    int ii = sII[r], jj = sJJ[r];
                    const float* xrow = xf + (size_t)jj * NB;
                    float* arow = agg + (size_t)ii * NB;
#pragma unroll
                    for (int nt = 0; nt < 4; nt++) {
                        int c = ng * 32 + nt * 8 + 2 * q;
                        float2 xv = *(const float2*)(xrow + c);
                        float2 bv = *(const float2*)&sB2[c];
                        float v0 = (acc[mt][nt][2 * half]     + bv.x) * rc * xv.x;
                        float v1 = (acc[mt][nt][2 * half + 1] + bv.y) * rc * xv.y;
                        red_add_v2(arow + c, v0, v1);
                    }
                }
            }
        }
        __syncthreads();
    }
}

// ---------------- head ----------------
__global__ void head_final(const float* __restrict__ h, const float* __restrict__ w2,
                           const int* __restrict__ batch, float* __restrict__ out, int M) {
    int w = (blockIdx.x * blockDim.x + threadIdx.x) >> 5;
    int lane = threadIdx.x & 31;
    if (w >= M) return;
    float4 v = ((const float4*)(h + (size_t)w * NB))[lane];
    float4 ww = ((const float4*)w2)[lane];
    float s = siluf(v.x) * ww.x + siluf(v.y) * ww.y + siluf(v.z) * ww.z + siluf(v.w) * ww.w;
#pragma unroll
    for (int o2 = 16; o2 > 0; o2 >>= 1) s += __shfl_xor_sync(0xffffffffu, s, o2);
    if (lane == 0) atomicAdd(&out[batch[w]], s);
}

// ---------------- launch ----------------
typedef void (*ngemm_fn)(const float*, const float*, const float*, float*, int, int);

extern "C" void kernel_launch(void* const* d_in, const int* in_sizes, int n_in,
                              void* d_out, int out_size)
{
    const int*   z         = (const int*)d_in[0];
    const int*   z_res     = (const int*)d_in[1];
    const float* pos       = (const float*)d_in[2];
    const int*   idx_i     = (const int*)d_in[3];
    const int*   idx_j     = (const int*)d_in[4];
    const int*   edge_attr = (const int*)d_in[5];
    const int*   batch     = (const int*)d_in[6];
    const float* ele_emb   = (const float*)d_in[7];
    const float* res_emb   = (const float*)d_in[8];
    const float* edge_emb  = (const float*)d_in[9];
    const float* in2f_W    = (const float*)d_in[10];
    const float* filt_W1   = (const float*)d_in[11];
    const float* filt_b1   = (const float*)d_in[12];
    const float* filt_W2   = (const float*)d_in[13];
    const float* filt_b2   = (const float*)d_in[14];
    const float* f2out_W1  = (const float*)d_in[15];
    const float* f2out_b1  = (const float*)d_in[16];
    const float* f2out_W2  = (const float*)d_in[17];
    const float* f2out_b2  = (const float*)d_in[18];
    const float* head_W1   = (const float*)d_in[19];
    const float* head_b1   = (const float*)d_in[20];
    const float* head_W2   = (const float*)d_in[21];
    float* out = (float*)d_out;

    const int N = in_sizes[0];
    const int E = in_sizes[3];

    int *pCnt, *pCi, *pCj;
    float *pRc, *pF, *pX, *pXf, *pAgg;
    cudaGetSymbolAddress((void**)&pCnt, g_cnt);
    cudaGetSymbolAddress((void**)&pCi, g_ci);
    cudaGetSymbolAddress((void**)&pCj, g_cj);
    cudaGetSymbolAddress((void**)&pRc, g_rc);
    cudaGetSymbolAddress((void**)&pF, g_F);
    cudaGetSymbolAddress((void**)&pX, g_x);
    cudaGetSymbolAddress((void**)&pXf, g_xf);
    cudaGetSymbolAddress((void**)&pAgg, g_agg);

    ngemm_fn f_plain = hmma_node_gemm<0>;
    ngemm_fn f_head  = hmma_node_gemm<2>;

    cudaFuncSetAttribute((const void*)f_plain, cudaFuncAttributeMaxDynamicSharedMemorySize, NODE_SMEM_BYTES);
    cudaFuncSetAttribute((const void*)f_head,  cudaFuncAttributeMaxDynamicSharedMemorySize, NODE_SMEM_BYTES);
    cudaFuncSetAttribute((const void*)hmma_f2out, cudaFuncAttributeMaxDynamicSharedMemorySize, NODE2_SMEM_BYTES);
    cudaFuncSetAttribute((const void*)edge_kernel, cudaFuncAttributeMaxDynamicSharedMemorySize, EDGE_SMEM_BYTES);

    int nsm = 148;
    cudaDeviceGetAttribute(&nsm, cudaDevAttrMultiProcessorCount, 0);
    const int ntiles = (N + 127) / 128;

    prep_zero<<<1, 32>>>();
    edge_compact<<<(E + 255) / 256, 256>>>(pos, idx_i, idx_j, edge_attr, edge_emb, E);
    embed_zero<<<(N * NB + 255) / 256, 256>>>(z, z_res, ele_emb, res_emb, pX, pAgg, out, N, out_size);

    for (int it = 0; it < 6; it++) {
        f_plain<<<nsm, 1024, NODE_SMEM_BYTES>>>(
            pX, in2f_W + (size_t)it * NB * NB, nullptr, pXf, N, ntiles);
        edge_kernel<<<nsm, 512, EDGE_SMEM_BYTES>>>(
            pCi, pCj,
            filt_W1 + (size_t)it * NRBF * NB, filt_b1 + (size_t)it * NB,
            filt_W2 + (size_t)it * NB * NB,  filt_b2 + (size_t)it * NB,
            pF, pRc, pXf, pAgg, pCnt);
        hmma_f2out<<<nsm, 1024, NODE2_SMEM_BYTES>>>(
            pAgg, f2out_W1 + (size_t)it * NB * NB, f2out_b1 + (size_t)it * NB,
            f2out_W2 + (size_t)it * NB * NB, f2out_b2 + (size_t)it * NB,
            pX, (it < 5) ? pAgg : nullptr, N, ntiles);
    }

    f_head<<<nsm, 1024, NODE_SMEM_BYTES>>>(pX, head_W1, head_b1, pXf, N, ntiles);
    head_final<<<(N + 7) / 8, 256>>>(pXf, head_W2, batch, out, N);
}

// round 16
// speedup vs baseline: 1.1748x; 1.1748x over previous
#include <cuda_runtime.h>
#include <cuda_bf16.h>
#include <stdint.h>
#include <math.h>

#define NATOMS 100000
#define NEDGES 1600000
#define NB 128
#define NRBF 32
#define CUTOFF_F 10.0f
#define PI_F 3.14159265358979f
#define LOG2_F 0.69314718055994531f

// ---------------- scratch (static __device__, no allocations) ----------------
__device__ int   g_cnt;
__device__ int   g_ci[NEDGES];
__device__ int   g_cj[NEDGES];
__device__ float g_rc[NEDGES];
__device__ float g_F[(size_t)NEDGES * NRBF];
__device__ float g_x[(size_t)NATOMS * NB];
__device__ float g_xf[(size_t)NATOMS * NB];
__device__ float g_agg[(size_t)NATOMS * NB];

// ---------------- math helpers ----------------
__device__ __forceinline__ float sspf(float v) {
    float ex = __expf(-fabsf(v));
    return fmaxf(v, 0.0f) + __logf(1.0f + ex) - LOG2_F;
}

__device__ __forceinline__ float siluf(float v) {
    return v * (1.0f / (1.0f + __expf(-v)));
}

__device__ __forceinline__ void red_add_v2(float* p, float a, float b) {
    asm volatile("red.global.add.v2.f32 [%0], {%1,%2};"
                 :: "l"(p), "f"(a), "f"(b) : "memory");
}

__device__ __forceinline__ void bar_grp(int id) {
    asm volatile("bar.sync %0, %1;" :: "r"(id), "r"(256) : "memory");
}

// HMMA bf16: D(f32) += A(16x16 bf16) * B(16x8 bf16)   [layout validated R5/R6]
__device__ __forceinline__ void mma_bf16(float* c, const uint32_t* a, const uint32_t* b) {
    asm volatile(
        "mma.sync.aligned.m16n8k16.row.col.f32.bf16.bf16.f32 "
        "{%0,%1,%2,%3}, {%4,%5,%6,%7}, {%8,%9}, {%0,%1,%2,%3};"
        : "+f"(c[0]), "+f"(c[1]), "+f"(c[2]), "+f"(c[3])
        : "r"(a[0]), "r"(a[1]), "r"(a[2]), "r"(a[3]), "r"(b[0]), "r"(b[1]));
}

__device__ __forceinline__ void bf16_split(float v, __nv_bfloat16& hi, __nv_bfloat16& lo) {
    hi = __float2bfloat16(v);
    lo = __float2bfloat16(v - __bfloat162float(hi));
}

// ---------------- smem byte offsets for edge kernel (2 groups, 64-edge tiles) ----------------
#define SM_B1    0        // 128 f32
#define SM_B2    512
#define SM_RC    1024     // 2 x 64 f32
#define SM_II    1536     // 2 x 64 i32
#define SM_JJ    2048
#define SM_W1HI  2560     // [n][k] 128 x 40 bf16 = 10240
#define SM_W1LO  12800
#define SM_WHI   23040    // [n][k] 128 x 136 bf16 = 34816
#define SM_WLO   57856
#define SM_FHI   92672    // 2 x (64 x 40 bf16 = 5120)
#define SM_FLO   102912
#define SM_HHI   113152   // 2 x (64 x 136 bf16 = 17408)
#define SM_HLO   147968
#define EDGE_SMEM_BYTES 182784

// ---------------- smem byte offsets for node gemm kernel ----------------
#define NSM_B    0
#define NSM_INHI 512
#define NSM_INLO 35328
#define NSM_WHI  70144
#define NSM_WLO  104960
#define NODE_SMEM_BYTES 139776

// ---------------- smem byte offsets for fused f2out kernel ----------------
#define N2_B1    0
#define N2_B2    512
#define N2_INHI  1024
#define N2_INLO  35840
#define N2_W1HI  70656
#define N2_W1LO  105472
#define N2_W2HI  140288
#define N2_W2LO  175104
#define NODE2_SMEM_BYTES 209920

// ---------------- prep kernels ----------------
__global__ void prep_zero() {
    if (threadIdx.x == 0) g_cnt = 0;
}

__global__ void edge_compact(const float* __restrict__ pos,
                             const int* __restrict__ idx_i,
                             const int* __restrict__ idx_j,
                             const int* __restrict__ edge_attr,
                             const float* __restrict__ edge_emb, int E) {
    int e = blockIdx.x * blockDim.x + threadIdx.x;
    int lane = threadIdx.x & 31;
    bool active = false;
    int a = 0, b = 0;
    float dd = 0.f;
    if (e < E) {
        a = idx_i[e]; b = idx_j[e];
        float dx = pos[a * 3 + 0] - pos[b * 3 + 0];
        float dy = pos[a * 3 + 1] - pos[b * 3 + 1];
        float dz = pos[a * 3 + 2] - pos[b * 3 + 2];
        dd = sqrtf(dx * dx + dy * dy + dz * dz);
        active = (dd < CUTOFF_F);
    }
    unsigned mask = __ballot_sync(0xffffffffu, active);
    if (!active) return;
    int leader = __ffs(mask) - 1;
    int rank = __popc(mask & ((1u << lane) - 1));
    int base = 0;
    if (lane == leader) base = atomicAdd(&g_cnt, __popc(mask));
    base = __shfl_sync(mask, base, leader);
    int p = base + rank;

    g_ci[p] = a;
    g_cj[p] = b;
    g_rc[p] = 0.5f * (__cosf(dd * (PI_F / CUTOFF_F)) + 1.0f);

    const float width = CUTOFF_F / 31.0f;
    const float coeff = -0.5f / (width * width);
    const float* emb = edge_emb + edge_attr[e] * NRBF;
    float4* dst = (float4*)(g_F + (size_t)p * NRBF);
#pragma unroll
    for (int j = 0; j < 8; j++) {
        float4 v;
        float u0 = dd - (float)(4 * j + 0) * width;
        float u1 = dd - (float)(4 * j + 1) * width;
        float u2 = dd - (float)(4 * j + 2) * width;
        float u3 = dd - (float)(4 * j + 3) * width;
        v.x = __expf(coeff * u0 * u0) + emb[4 * j + 0];
        v.y = __expf(coeff * u1 * u1) + emb[4 * j + 1];
        v.z = __expf(coeff * u2 * u2) + emb[4 * j + 2];
        v.w = __expf(coeff * u3 * u3) + emb[4 * j + 3];
        dst[j] = v;
    }
}

__global__ void embed_zero(const int* __restrict__ z, const int* __restrict__ z_res,
                           const float* __restrict__ ele_emb, const float* __restrict__ res_emb,
                           float* __restrict__ x, float* __restrict__ agg,
                           float* __restrict__ outbuf, int N, int out_n) {
    int t = blockIdx.x * blockDim.x + threadIdx.x;
    if (t < out_n) outbuf[t] = 0.f;
    if (t >= N * NB) return;
    int n = t >> 7, c = t & 127;
    agg[t] = 0.f;
    x[t] = ele_emb[z[n] * NB + c] + res_emb[z_res[n] * NB + c];
}

// ---------------- persistent HMMA node GEMM (1024 thr, R10/R15-proven) ----------------
// PRE: 0=none, 2=L2-normalize then silu
template <int PRE>
__global__ __launch_bounds__(1024, 1) void hmma_node_gemm(
    const float* __restrict__ in, const float* __restrict__ W,
    const float* __restrict__ bias,
    float* __restrict__ out, int M, int ntiles)
{
    extern __shared__ char smch[];
    float* sB = (float*)(smch + NSM_B);

    const int t = threadIdx.x;
    const int wid = t >> 5;
    const int lane = t & 31;
    const int q = lane & 3;
    const int lr = lane >> 2;

    if (t < 128) sB[t] = bias ? bias[t] : 0.f;
#pragma unroll
    for (int i = 0; i < 4; i++) {
        int idx4 = i * 1024 + t;
        int k = idx4 >> 5;
        int n0 = (idx4 & 31) * 4;
        float4 w = ((const float4*)W)[idx4];
        float vs[4] = { w.x, w.y, w.z, w.w };
#pragma unroll
        for (int d = 0; d < 4; d++) {
            __nv_bfloat16 hi, lo;
            bf16_split(vs[d], hi, lo);
            size_t off = ((size_t)(n0 + d) * 136 + k) * 2;
            *(__nv_bfloat16*)(smch + NSM_WHI + off) = hi;
            *(__nv_bfloat16*)(smch + NSM_WLO + off) = lo;
        }
    }
    __syncthreads();

    const int mg = wid & 3;
    const int ng = wid >> 2;

    for (int tile = blockIdx.x; tile < ntiles; tile += gridDim.x) {
        const int m0 = tile * 128;

        {
            int r = t >> 3, cq = (t & 7) * 16;
            const float4* src = (const float4*)(in + (size_t)(m0 + r) * NB + cq);
            bool ok = (m0 + r < M);
            float4 fv[4];
#pragma unroll
            for (int j = 0; j < 4; j++)
                fv[j] = ok ? src[j] : make_float4(0.f, 0.f, 0.f, 0.f);
            float scale = 1.0f;
            if (PRE == 2) {
                float ss = 0.f;
#pragma unroll
                for (int j = 0; j < 4; j++)
                    ss += fv[j].x * fv[j].x + fv[j].y * fv[j].y + fv[j].z * fv[j].z + fv[j].w * fv[j].w;
                ss += __shfl_xor_sync(0xffffffffu, ss, 1);
                ss += __shfl_xor_sync(0xffffffffu, ss, 2);
                ss += __shfl_xor_sync(0xffffffffu, ss, 4);
                scale = 1.0f / fmaxf(sqrtf(ss), 1e-12f);
            }
#pragma unroll
            for (int j = 0; j < 4; j++) {
                float4 f = fv[j];
                if (PRE == 2) {
                    f.x = siluf(f.x * scale); f.y = siluf(f.y * scale);
                    f.z = siluf(f.z * scale); f.w = siluf(f.w * scale);
                }
                __nv_bfloat162 h0, h1, l0, l1;
                bf16_split(f.x, h0.x, l0.x); bf16_split(f.y, h0.y, l0.y);
                bf16_split(f.z, h1.x, l1.x); bf16_split(f.w, h1.y, l1.y);
                size_t off = ((size_t)r * 136 + cq + j * 4) * 2;
                *(uint2*)(smch + NSM_INHI + off) = make_uint2(*(uint32_t*)&h0, *(uint32_t*)&h1);
                *(uint2*)(smch + NSM_INLO + off) = make_uint2(*(uint32_t*)&l0, *(uint32_t*)&l1);
            }
        }
        __syncthreads();

        float acc[2][2][4];
#pragma unroll
        for (int mt = 0; mt < 2; mt++)
#pragma unroll
            for (int nt = 0; nt < 2; nt++)
#pragma unroll
                for (int v = 0; v < 4; v++) acc[mt][nt][v] = 0.f;

#pragma unroll 2
        for (int ks = 0; ks < 8; ks++) {
            const int k0 = ks * 16;
            uint32_t ahi[2][4], alo[2][4];
#pragma unroll
            for (int mt = 0; mt < 2; mt++) {
                int m = mg * 32 + mt * 16 + lr;
                size_t o0 = ((size_t)m * 136 + k0 + 2 * q) * 2;
                size_t o1 = ((size_t)(m + 8) * 136 + k0 + 2 * q) * 2;
                ahi[mt][0] = *(const uint32_t*)(smch + NSM_INHI + o0);
                ahi[mt][1] = *(const uint32_t*)(smch + NSM_INHI + o1);
                ahi[mt][2] = *(const uint32_t*)(smch + NSM_INHI + o0 + 16);
                ahi[mt][3] = *(const uint32_t*)(smch + NSM_INHI + o1 + 16);
                alo[mt][0] = *(const uint32_t*)(smch + NSM_INLO + o0);
                alo[mt][1] = *(const uint32_t*)(smch + NSM_INLO + o1);
                alo[mt][2] = *(const uint32_t*)(smch + NSM_INLO + o0 + 16);
                alo[mt][3] = *(const uint32_t*)(smch + NSM_INLO + o1 + 16);
            }
#pragma unroll
            for (int nt = 0; nt < 2; nt++) {
                int n = ng * 16 + nt * 8 + lr;
                size_t ob = ((size_t)n * 136 + k0 + 2 * q) * 2;
                uint32_t bhi[2] = { *(const uint32_t*)(smch + NSM_WHI + ob),
                                    *(const uint32_t*)(smch + NSM_WHI + ob + 16) };
                uint32_t blo[2] = { *(const uint32_t*)(smch + NSM_WLO + ob),
                                    *(const uint32_t*)(smch + NSM_WLO + ob + 16) };
#pragma unroll
                for (int mt = 0; mt < 2; mt++) {
                    mma_bf16(acc[mt][nt], ahi[mt], bhi);
                    mma_bf16(acc[mt][nt], ahi[mt], blo);
                    mma_bf16(acc[mt][nt], alo[mt], bhi);
                }
            }
        }

#pragma unroll
        for (int mt = 0; mt < 2; mt++) {
#pragma unroll
            for (int half = 0; half < 2; half++) {
                int rr = mg * 32 + mt * 16 + lr + 8 * half;
                int m = m0 + rr;
                if (m < M) {
                    float* orow = out + (size_t)m * NB;
#pragma unroll
                    for (int nt = 0; nt < 2; nt++) {
                        int c = ng * 16 + nt * 8 + 2 * q;
                        float2 bv = *(const float2*)&sB[c];
                        *(float2*)(orow + c) = make_float2(acc[mt][nt][2 * half] + bv.x,
                                                           acc[mt][nt][2 * half + 1] + bv.y);
                    }
                }
            }
        }
        __syncthreads();
    }
}

// ---------------- fused f2out (512 thr, R9-proven): x += ssp(agg@W1+b1)@W2+b2 ; zero agg ----------------
__global__ __launch_bounds__(512, 1) void hmma_f2out(
    const float* __restrict__ agg_in, const float* __restrict__ W1,
    const float* __restrict__ b1, const float* __restrict__ W2,
    const float* __restrict__ b2, float* __restrict__ x,
    float* __restrict__ aggz, int M, int ntiles)
{
    extern __shared__ char smch[];
    float* sB1 = (float*)(smch + N2_B1);
    float* sB2 = (float*)(smch + N2_B2);

    const int t = threadIdx.x;
    const int wid = t >> 5;
    const int lane = t & 31;
    const int q = lane & 3;
    const int lr = lane >> 2;

    if (t < 128) { sB1[t] = b1[t]; sB2[t] = b2[t]; }
#pragma unroll
    for (int i = 0; i < 8; i++) {
        int idx4 = i * 512 + t;
        int k = idx4 >> 5;
        int n0 = (idx4 & 31) * 4;
        float4 w1 = ((const float4*)W1)[idx4];
        float4 w2 = ((const float4*)W2)[idx4];
        float v1[4] = { w1.x, w1.y, w1.z, w1.w };
        float v2[4] = { w2.x, w2.y, w2.z, w2.w };
#pragma unroll
        for (int d = 0; d < 4; d++) {
            size_t off = ((size_t)(n0 + d) * 136 + k) * 2;
            __nv_bfloat16 hi, lo;
            bf16_split(v1[d], hi, lo);
            *(__nv_bfloat16*)(smch + N2_W1HI + off) = hi;
            *(__nv_bfloat16*)(smch + N2_W1LO + off) = lo;
            bf16_split(v2[d], hi, lo);
            *(__nv_bfloat16*)(smch + N2_W2HI + off) = hi;
            *(__nv_bfloat16*)(smch + N2_W2LO + off) = lo;
        }
    }
    __syncthreads();

    const int mg = wid & 3;
    const int ng = wid >> 2;

    for (int tile = blockIdx.x; tile < ntiles; tile += gridDim.x) {
        const int m0 = tile * 128;

        {
            int r = t >> 2, cq = (t & 3) * 32;
            const float4* src = (const float4*)(agg_in + (size_t)(m0 + r) * NB + cq);
            bool ok = (m0 + r < M);
#pragma unroll
            for (int j = 0; j < 8; j++) {
                float4 f = ok ? src[j] : make_float4(0.f, 0.f, 0.f, 0.f);
                __nv_bfloat162 h0, h1, l0, l1;
                bf16_split(f.x, h0.x, l0.x); bf16_split(f.y, h0.y, l0.y);
                bf16_split(f.z, h1.x, l1.x); bf16_split(f.w, h1.y, l1.y);
                size_t off = ((size_t)r * 136 + cq + j * 4) * 2;
                *(uint2*)(smch + N2_INHI + off) = make_uint2(*(uint32_t*)&h0, *(uint32_t*)&h1);
                *(uint2*)(smch + N2_INLO + off) = make_uint2(*(uint32_t*)&l0, *(uint32_t*)&l1);
            }
        }
        __syncthreads();

        float acc[2][4][4];
#pragma unroll
        for (int mt = 0; mt < 2; mt++)
#pragma unroll
            for (int nt = 0; nt < 4; nt++)
#pragma unroll
                for (int v = 0; v < 4; v++) acc[mt][nt][v] = 0.f;

        // phase 1: C1 = agg @ W1
#pragma unroll 2
        for (int ks = 0; ks < 8; ks++) {
            const int k0 = ks * 16;
            uint32_t ahi[2][4], alo[2][4];
#pragma unroll
            for (int mt = 0; mt < 2; mt++) {
                int m = mg * 32 + mt * 16 + lr;
                size_t o0 = ((size_t)m * 136 + k0 + 2 * q) * 2;
                size_t o1 = ((size_t)(m + 8) * 136 + k0 + 2 * q) * 2;
                ahi[mt][0] = *(const uint32_t*)(smch + N2_INHI + o0);
                ahi[mt][1] = *(const uint32_t*)(smch + N2_INHI + o1);
                ahi[mt][2] = *(const uint32_t*)(smch + N2_INHI + o0 + 16);
                ahi[mt][3] = *(const uint32_t*)(smch + N2_INHI + o1 + 16);
                alo[mt][0] = *(const uint32_t*)(smch + N2_INLO + o0);
                alo[mt][1] = *(const uint32_t*)(smch + N2_INLO + o1);
                alo[mt][2] = *(const uint32_t*)(smch + N2_INLO + o0 + 16);
                alo[mt][3] = *(const uint32_t*)(smch + N2_INLO + o1 + 16);
            }
#pragma unroll
            for (int nt = 0; nt < 4; nt++) {
                int n = ng * 32 + nt * 8 + lr;
                size_t ob = ((size_t)n * 136 + k0 + 2 * q) * 2;
                uint32_t bhi[2] = { *(const uint32_t*)(smch + N2_W1HI + ob),
                                    *(const uint32_t*)(smch + N2_W1HI + ob + 16) };
                uint32_t blo[2] = { *(const uint32_t*)(smch + N2_W1LO + ob),
                                    *(const uint32_t*)(smch + N2_W1LO + ob + 16) };
#pragma unroll
                for (int mt = 0; mt < 2; mt++) {
                    mma_bf16(acc[mt][nt], ahi[mt], bhi);
                    mma_bf16(acc[mt][nt], ahi[mt], blo);
                    mma_bf16(acc[mt][nt], alo[mt], bhi);
                }
            }
        }
        __syncthreads();  // all phase-1 reads of IN done

        // H = ssp(C1 + b1) -> overwrite IN buffers
#pragma unroll
        for (int mt = 0; mt < 2; mt++) {
#pragma unroll
            for (int half = 0; half < 2; half++) {
                int rr = mg * 32 + mt * 16 + lr + 8 * half;
#pragma unroll
                for (int nt = 0; nt < 4; nt++) {
                    int c = ng * 32 + nt * 8 + 2 * q;
                    float2 bv = *(const float2*)&sB1[c];
                    float h0 = sspf(acc[mt][nt][2 * half] + bv.x);
                    float h1 = sspf(acc[mt][nt][2 * half + 1] + bv.y);
                    __nv_bfloat162 hh, ll;
                    bf16_split(h0, hh.x, ll.x);
                    bf16_split(h1, hh.y, ll.y);
                    size_t off = ((size_t)rr * 136 + c) * 2;
                    *(uint32_t*)(smch + N2_INHI + off) = *(uint32_t*)&hh;
                    *(uint32_t*)(smch + N2_INLO + off) = *(uint32_t*)&ll;
                }
            }
        }
        __syncthreads();

        // phase 2: C2 = H @ W2
#pragma unroll
        for (int mt = 0; mt < 2; mt++)
#pragma unroll
            for (int nt = 0; nt < 4; nt++)
#pragma unroll
                for (int v = 0; v < 4; v++) acc[mt][nt][v] = 0.f;

#pragma unroll 2
        for (int ks = 0; ks < 8; ks++) {
            const int k0 = ks * 16;
            uint32_t ahi[2][4], alo[2][4];
#pragma unroll
            for (int mt = 0; mt < 2; mt++) {
                int m = mg * 32 + mt * 16 + lr;
                size_t o0 = ((size_t)m * 136 + k0 + 2 * q) * 2;
                size_t o1 = ((size_t)(m + 8) * 136 + k0 + 2 * q) * 2;
                ahi[mt][0] = *(const uint32_t*)(smch + N2_INHI + o0);
                ahi[mt][1] = *(const uint32_t*)(smch + N2_INHI + o1);
                ahi[mt][2] = *(const uint32_t*)(smch + N2_INHI + o0 + 16);
                ahi[mt][3] = *(const uint32_t*)(smch + N2_INHI + o1 + 16);
                alo[mt][0] = *(const uint32_t*)(smch + N2_INLO + o0);
                alo[mt][1] = *(const uint32_t*)(smch + N2_INLO + o1);
                alo[mt][2] = *(const uint32_t*)(smch + N2_INLO + o0 + 16);
                alo[mt][3] = *(const uint32_t*)(smch + N2_INLO + o1 + 16);
            }
#pragma unroll
            for (int nt = 0; nt < 4; nt++) {
                int n = ng * 32 + nt * 8 + lr;
                size_t ob = ((size_t)n * 136 + k0 + 2 * q) * 2;
                uint32_t bhi[2] = { *(const uint32_t*)(smch + N2_W2HI + ob),
                                    *(const uint32_t*)(smch + N2_W2HI + ob + 16) };
                uint32_t blo[2] = { *(const uint32_t*)(smch + N2_W2LO + ob),
                                    *(const uint32_t*)(smch + N2_W2LO + ob + 16) };
#pragma unroll
                for (int mt = 0; mt < 2; mt++) {
                    mma_bf16(acc[mt][nt], ahi[mt], bhi);
                    mma_bf16(acc[mt][nt], ahi[mt], blo);
                    mma_bf16(acc[mt][nt], alo[mt], bhi);
                }
            }
        }

        // epilogue: x += C2 + b2 ; zero agg
#pragma unroll
        for (int mt = 0; mt < 2; mt++) {
#pragma unroll
            for (int half = 0; half < 2; half++) {
                int rr = mg * 32 + mt * 16 + lr + 8 * half;
                int m = m0 + rr;
                if (m < M) {
                    float* xrow = x + (size_t)m * NB;
                    float* zrow = aggz ? aggz + (size_t)m * NB : 0;
#pragma unroll
                    for (int nt = 0; nt < 4; nt++) {
                        int c = ng * 32 + nt * 8 + 2 * q;
                        float2 bv = *(const float2*)&sB2[c];
                        float2 xv = *(const float2*)(xrow + c);
                        *(float2*)(xrow + c) = make_float2(xv.x + acc[mt][nt][2 * half] + bv.x,
                                                           xv.y + acc[mt][nt][2 * half + 1] + bv.y);
                        if (aggz) *(float2*)(zrow + c) = make_float2(0.f, 0.f);
                    }
                }
            }
        }
        __syncthreads();
    }
}

// ---------------- persistent fused edge kernel: 2 independent 256-thr groups, 64-edge tiles ----------------
__global__ __launch_bounds__(512, 1) void edge_kernel(
    const int* __restrict__ ci, const int* __restrict__ cj,
    const float* __restrict__ W1, const float* __restrict__ b1,
    const float* __restrict__ W2, const float* __restrict__ b2,
    const float* __restrict__ Ff, const float* __restrict__ rcut,
    const float* __restrict__ xf, float* __restrict__ agg,
    const int* __restrict__ cntPtr)
{
    extern __shared__ char smch[];
    float* sB1 = (float*)(smch + SM_B1);
    float* sB2 = (float*)(smch + SM_B2);

    const int E = *cntPtr;
    const int ntiles = (E + 63) >> 6;

    const int t = threadIdx.x;
    const int wid = t >> 5;
    const int lane = t & 31;
    const int q = lane & 3;
    const int lr = lane >> 2;

    // group decomposition
    const int grp = wid >> 3;          // 0 or 1
    const int gwid = wid & 7;          // warp within group
    const int tg = t & 255;            // thread within group
    const int barid = grp + 1;

    // group-local buffer bases
    float* sRC = (float*)(smch + SM_RC + grp * 256);
    int*   sII = (int*)(smch + SM_II + grp * 256);
    int*   sJJ = (int*)(smch + SM_JJ + grp * 256);
    char*  sFHI = smch + SM_FHI + grp * 5120;
    char*  sFLO = smch + SM_FLO + grp * 5120;
    char*  sHHI = smch + SM_HHI + grp * 17408;
    char*  sHLO = smch + SM_HLO + grp * 17408;

    // shared one-time staging (all 512 threads)
    if (t < 128) { sB1[t] = b1[t]; sB2[t] = b2[t]; }
#pragma unroll
    for (int i = 0; i < 2; i++) {
        int idx4 = i * 512 + t;
        int k = idx4 >> 5;
        int n0 = (idx4 & 31) * 4;
        float4 w = ((const float4*)W1)[idx4];
        float vs[4] = { w.x, w.y, w.z, w.w };
#pragma unroll
        for (int d = 0; d < 4; d++) {
            __nv_bfloat16 hi, lo;
            bf16_split(vs[d], hi, lo);
            size_t off = ((size_t)(n0 + d) * 40 + k) * 2;
            *(__nv_bfloat16*)(smch + SM_W1HI + off) = hi;
            *(__nv_bfloat16*)(smch + SM_W1LO + off) = lo;
        }
    }
#pragma unroll
    for (int i = 0; i < 8; i++) {
        int idx4 = i * 512 + t;
        int k = idx4 >> 5;
        int n0 = (idx4 & 31) * 4;
        float4 w = ((const float4*)W2)[idx4];
        float vs[4] = { w.x, w.y, w.z, w.w };
#pragma unroll
        for (int d = 0; d < 4; d++) {
            __nv_bfloat16 hi, lo;
            bf16_split(vs[d], hi, lo);
            size_t off = ((size_t)(n0 + d) * 136 + k) * 2;
            *(__nv_bfloat16*)(smch + SM_WHI + off) = hi;
            *(__nv_bfloat16*)(smch + SM_WLO + off) = lo;
        }
    }
    __syncthreads();

    // phase-1 warp tiling within group: pm rows(16), pn cols(64)
    const int pm = gwid & 3;
    const int pn = gwid >> 2;
    // phase-2 warp tiling within group: mg rows(32), ng cols(32)
    const int mg = gwid & 1;
    const int ng = gwid >> 1;

    for (int tile = blockIdx.x * 2 + grp; tile < ntiles; tile += gridDim.x * 2) {
        const int eb = tile * 64;

        // ---- stage F (64 rows) + per-edge scalars (group-local)
        {
            int r = tg >> 2, kq = (tg & 3) * 8;
            float4 f0 = make_float4(0.f, 0.f, 0.f, 0.f);
            float4 f1 = make_float4(0.f, 0.f, 0.f, 0.f);
            if (eb + r < E) {
                const float4* src = (const float4*)(Ff + (size_t)(eb + r) * NRBF + kq);
                f0 = src[0]; f1 = src[1];
            }
            __nv_bfloat162 h0, h1, h2, h3, l0, l1, l2, l3;
            bf16_split(f0.x, h0.x, l0.x); bf16_split(f0.y, h0.y, l0.y);
            bf16_split(f0.z, h1.x, l1.x); bf16_split(f0.w, h1.y, l1.y);
            bf16_split(f1.x, h2.x, l2.x); bf16_split(f1.y, h2.y, l2.y);
            bf16_split(f1.z, h3.x, l3.x); bf16_split(f1.w, h3.y, l3.y);
            size_t off = ((size_t)r * 40 + kq) * 2;
            uint4 uh = make_uint4(*(uint32_t*)&h0, *(uint32_t*)&h1, *(uint32_t*)&h2, *(uint32_t*)&h3);
            uint4 ul = make_uint4(*(uint32_t*)&l0, *(uint32_t*)&l1, *(uint32_t*)&l2, *(uint32_t*)&l3);
            *(uint4*)(sFHI + off) = uh;
            *(uint4*)(sFLO + off) = ul;
        }
        if (tg < 64) {
            int e = eb + tg;
            float rcv = 0.f; int iiv = 0, jjv = 0;
            if (e < E) { rcv = rcut[e]; iiv = ci[e]; jjv = cj[e]; }
            sRC[tg] = rcv; sII[tg] = iiv; sJJ[tg] = jjv;
        }
        bar_grp(barid);

        // ---- phase 1: warp = rows pm*16..+16, cols pn*64..+64
        {
            const int m0 = pm * 16, n0 = pn * 64;
            uint32_t ahi[2][4], alo[2][4];
#pragma unroll
            for (int ks = 0; ks < 2; ks++) {
                size_t o0 = ((size_t)(m0 + lr) * 40 + ks * 16 + 2 * q) * 2;
                size_t o1 = o0 + 640;
                ahi[ks][0] = *(const uint32_t*)(sFHI + o0);
                ahi[ks][1] = *(const uint32_t*)(sFHI + o1);
                ahi[ks][2] = *(const uint32_t*)(sFHI + o0 + 16);
                ahi[ks][3] = *(const uint32_t*)(sFHI + o1 + 16);
                alo[ks][0] = *(const uint32_t*)(sFLO + o0);
                alo[ks][1] = *(const uint32_t*)(sFLO + o1);
                alo[ks][2] = *(const uint32_t*)(sFLO + o0 + 16);
                alo[ks][3] = *(const uint32_t*)(sFLO + o1 + 16);
            }
#pragma unroll
            for (int nt = 0; nt < 8; nt++) {
                int n = n0 + nt * 8 + lr;
                float c[4] = { 0.f, 0.f, 0.f, 0.f };
#pragma unroll
                for (int ks = 0; ks < 2; ks++) {
                    size_t ob = ((size_t)n * 40 + ks * 16 + 2 * q) * 2;
                    uint32_t bh[2] = { *(const uint32_t*)(smch + SM_W1HI + ob),
                                       *(const uint32_t*)(smch + SM_W1HI + ob + 16) };
                    uint32_t bl[2] = { *(const uint32_t*)(smch + SM_W1LO + ob),
                                       *(const uint32_t*)(smch + SM_W1LO + ob + 16) };
                    mma_bf16(c, ahi[ks], bh);
                    mma_bf16(c, ahi[ks], bl);
                    mma_bf16(c, alo[ks], bh);
                }
                int cc = n0 + nt * 8 + 2 * q;
                float2 bv = *(const float2*)&sB1[cc];
                float h00 = sspf(c[0] + bv.x), h01 = sspf(c[1] + bv.y);
                float h10 = sspf(c[2] + bv.x), h11 = sspf(c[3] + bv.y);
                __nv_bfloat162 p0, p1, e0, e1;
                bf16_split(h00, p0.x, e0.x); bf16_split(h01, p0.y, e0.y);
                bf16_split(h10, p1.x, e1.x); bf16_split(h11, p1.y, e1.y);
                size_t oh0 = ((size_t)(m0 + lr) * 136 + cc) * 2;
                size_t oh1 = oh0 + 136 * 8 * 2;
                *(uint32_t*)(sHHI + oh0) = *(uint32_t*)&p0;
                *(uint32_t*)(sHHI + oh1) = *(uint32_t*)&p1;
                *(uint32_t*)(sHLO + oh0) = *(uint32_t*)&e0;
                *(uint32_t*)(sHLO + oh1) = *(uint32_t*)&e1;
            }
        }
        bar_grp(barid);

        // ---- phase 2: warp = rows mg*32..+32, cols ng*32..+32
        {
            float acc[2][4][4];
#pragma unroll
            for (int mt = 0; mt < 2; mt++)
#pragma unroll
                for (int nt = 0; nt < 4; nt++)
#pragma unroll
                    for (int v = 0; v < 4; v++) acc[mt][nt][v] = 0.f;

#pragma unroll 2
            for (int ks = 0; ks < 8; ks++) {
                const int k0 = ks * 16;
                uint32_t ahi[2][4], alo[2][4];
#pragma unroll
                for (int mt = 0; mt < 2; mt++) {
                    int m = mg * 32 + mt * 16 + lr;
                    size_t o0 = ((size_t)m * 136 + k0 + 2 * q) * 2;
                    size_t o1 = ((size_t)(m + 8) * 136 + k0 + 2 * q) * 2;
                    ahi[mt][0] = *(const uint32_t*)(sHHI + o0);
                    ahi[mt][1] = *(const uint32_t*)(sHHI + o1);
                    ahi[mt][2] = *(const uint32_t*)(sHHI + o0 + 16);
                    ahi[mt][3] = *(const uint32_t*)(sHHI + o1 + 16);
                    alo[mt][0] = *(const uint32_t*)(sHLO + o0);
                    alo[mt][1] = *(const uint32_t*)(sHLO + o1);
                    alo[mt][2] = *(const uint32_t*)(sHLO + o0 + 16);
                    alo[mt][3] = *(const uint32_t*)(sHLO + o1 + 16);
                }
#pragma unroll
                for (int nt = 0; nt < 4; nt++) {
                    int n = ng * 32 + nt * 8 + lr;
                    size_t ob = ((size_t)n * 136 + k0 + 2 * q) * 2;
                    uint32_t bhi[2] = { *(const uint32_t*)(smch + SM_WHI + ob),
                                        *(const uint32_t*)(smch + SM_WHI + ob + 16) };
                    uint32_t blo[2] = { *(const uint32_t*)(smch + SM_WLO + ob),
                                        *(const uint32_t*)(smch + SM_WLO + ob + 16) };
#pragma unroll
                    for (int mt = 0; mt < 2; mt++) {
                        mma_bf16(acc[mt][nt], ahi[mt], bhi);
                        mma_bf16(acc[mt][nt], ahi[mt], blo);
                        mma_bf16(acc[mt][nt], alo[mt], bhi);
                    }
                }
            }

            // ---- epilogue: gather xf, scale, red.v2
#pragma unroll
            for (int mt = 0; mt < 2; mt++) {
#pragma unroll
                for (int half = 0; half < 2; half++) {
                    int r = mg * 32 + mt * 16 + lr + 8 * half;
                    float rc = sRC[r];
                    int ii = sII[r], jj = sJJ[r];
                    const float* xrow = xf + (size_t)jj * NB;
                    float* arow = agg + (size_t)ii * NB;
#pragma unroll
                    for (int nt = 0; nt < 4; nt++) {
                        int c = ng * 32 + nt * 8 + 2 * q;
                        float2 xv = *(const float2*)(xrow + c);
                        float2 bv = *(const float2*)&sB2[c];
                        float v0 = (acc[mt][nt][2 * half]     + bv.x) * rc * xv.x;
                        float v1 = (acc[mt][nt][2 * half + 1] + bv.y) * rc * xv.y;
                        red_add_v2(arow + c, v0, v1);
                    }
                }
            }
        }
        bar_grp(barid);
    }
}

// ---------------- head ----------------
__global__ void head_final(const float* __restrict__ h, const float* __restrict__ w2,
                           const int* __restrict__ batch, float* __restrict__ out, int M) {
    int w = (blockIdx.x * blockDim.x + threadIdx.x) >> 5;
    int lane = threadIdx.x & 31;
    if (w >= M) return;
    float4 v = ((const float4*)(h + (size_t)w * NB))[lane];
    float4 ww = ((const float4*)w2)[lane];
    float s = siluf(v.x) * ww.x + siluf(v.y) * ww.y + siluf(v.z) * ww.z + siluf(v.w) * ww.w;
#pragma unroll
    for (int o2 = 16; o2 > 0; o2 >>= 1) s += __shfl_xor_sync(0xffffffffu, s, o2);
    if (lane == 0) atomicAdd(&out[batch[w]], s);
}

// ---------------- launch ----------------
typedef void (*ngemm_fn)(const float*, const float*, const float*, float*, int, int);

extern "C" void kernel_launch(void* const* d_in, const int* in_sizes, int n_in,
                              void* d_out, int out_size)
{
    const int*   z         = (const int*)d_in[0];
    const int*   z_res     = (const int*)d_in[1];
    const float* pos       = (const float*)d_in[2];
    const int*   idx_i     = (const int*)d_in[3];
    const int*   idx_j     = (const int*)d_in[4];
    const int*   edge_attr = (const int*)d_in[5];
    const int*   batch     = (const int*)d_in[6];
    const float* ele_emb   = (const float*)d_in[7];
    const float* res_emb   = (const float*)d_in[8];
    const float* edge_emb  = (const float*)d_in[9];
    const float* in2f_W    = (const float*)d_in[10];
    const float* filt_W1   = (const float*)d_in[11];
    const float* filt_b1   = (const float*)d_in[12];
    const float* filt_W2   = (const float*)d_in[13];
    const float* filt_b2   = (const float*)d_in[14];
    const float* f2out_W1  = (const float*)d_in[15];
    const float* f2out_b1  = (const float*)d_in[16];
    const float* f2out_W2  = (const float*)d_in[17];
    const float* f2out_b2  = (const float*)d_in[18];
    const float* head_W1   = (const float*)d_in[19];
    const float* head_b1   = (const float*)d_in[20];
    const float* head_W2   = (const float*)d_in[21];
    float* out = (float*)d_out;

    const int N = in_sizes[0];
    const int E = in_sizes[3];

    int *pCnt, *pCi, *pCj;
    float *pRc, *pF, *pX, *pXf, *pAgg;
    cudaGetSymbolAddress((void**)&pCnt, g_cnt);
    cudaGetSymbolAddress((void**)&pCi, g_ci);
    cudaGetSymbolAddress((void**)&pCj, g_cj);
    cudaGetSymbolAddress((void**)&pRc, g_rc);
    cudaGetSymbolAddress((void**)&pF, g_F);
    cudaGetSymbolAddress((void**)&pX, g_x);
    cudaGetSymbolAddress((void**)&pXf, g_xf);
    cudaGetSymbolAddress((void**)&pAgg, g_agg);

    ngemm_fn f_plain = hmma_node_gemm<0>;
    ngemm_fn f_head  = hmma_node_gemm<2>;

    cudaFuncSetAttribute((const void*)f_plain, cudaFuncAttributeMaxDynamicSharedMemorySize, NODE_SMEM_BYTES);
    cudaFuncSetAttribute((const void*)f_head,  cudaFuncAttributeMaxDynamicSharedMemorySize, NODE_SMEM_BYTES);
    cudaFuncSetAttribute((const void*)hmma_f2out, cudaFuncAttributeMaxDynamicSharedMemorySize, NODE2_SMEM_BYTES);
    cudaFuncSetAttribute((const void*)edge_kernel, cudaFuncAttributeMaxDynamicSharedMemorySize, EDGE_SMEM_BYTES);

    int nsm = 148;
    cudaDeviceGetAttribute(&nsm, cudaDevAttrMultiProcessorCount, 0);
    const int ntiles = (N + 127) / 128;

    prep_zero<<<1, 32>>>();
    edge_compact<<<(E + 255) / 256, 256>>>(pos, idx_i, idx_j, edge_attr, edge_emb, E);
    embed_zero<<<(N * NB + 255) / 256, 256>>>(z, z_res, ele_emb, res_emb, pX, pAgg, out, N, out_size);

    for (int it = 0; it < 6; it++) {
        f_plain<<<nsm, 1024, NODE_SMEM_BYTES>>>(
            pX, in2f_W + (size_t)it * NB * NB, nullptr, pXf, N, ntiles);
        edge_kernel<<<nsm, 512, EDGE_SMEM_BYTES>>>(
            pCi, pCj,
            filt_W1 + (size_t)it * NRBF * NB, filt_b1 + (size_t)it * NB,
            filt_W2 + (size_t)it * NB * NB,  filt_b2 + (size_t)it * NB,
            pF, pRc, pXf, pAgg, pCnt);
        hmma_f2out<<<nsm, 512, NODE2_SMEM_BYTES>>>(
            pAgg, f2out_W1 + (size_t)it * NB * NB, f2out_b1 + (size_t)it * NB,
            f2out_W2 + (size_t)it * NB * NB, f2out_b2 + (size_t)it * NB,
            pX, (it < 5) ? pAgg : nullptr, N, ntiles);
    }

    f_head<<<nsm, 1024, NODE_SMEM_BYTES>>>(pX, head_W1, head_b1, pXf, N, ntiles);
    head_final<<<(N + 7) / 8, 256>>>(pXf, head_W2, batch, out, N);
}

// round 17
// speedup vs baseline: 1.2003x; 1.0217x over previous
#include <cuda_runtime.h>
#include <cuda_bf16.h>
#include <stdint.h>
#include <math.h>

#define NATOMS 100000
#define NEDGES 1600000
#define NB 128
#define NRBF 32
#define CUTOFF_F 10.0f
#define PI_F 3.14159265358979f
#define LOG2_F 0.69314718055994531f

// ---------------- scratch (static __device__, no allocations) ----------------
__device__ int   g_cnt;
__device__ int   g_ci[NEDGES];
__device__ int   g_cj[NEDGES];
__device__ float g_rc[NEDGES];
__device__ float g_F[(size_t)NEDGES * NRBF];
__device__ float g_x[(size_t)NATOMS * NB];
__device__ float g_xf[(size_t)NATOMS * NB];
__device__ float g_agg[(size_t)NATOMS * NB];

// ---------------- math helpers ----------------
__device__ __forceinline__ float sspf(float v) {
    float ex = __expf(-fabsf(v));
    return fmaxf(v, 0.0f) + __logf(1.0f + ex) - LOG2_F;
}

__device__ __forceinline__ float siluf(float v) {
    return v * (1.0f / (1.0f + __expf(-v)));
}

__device__ __forceinline__ void red_add_v2(float* p, float a, float b) {
    asm volatile("red.global.add.v2.f32 [%0], {%1,%2};"
                 :: "l"(p), "f"(a), "f"(b) : "memory");
}

__device__ __forceinline__ void bar_grp(int id) {
    asm volatile("bar.sync %0, %1;" :: "r"(id), "r"(256) : "memory");
}

// HMMA bf16: D(f32) += A(16x16 bf16) * B(16x8 bf16)   [layout validated R5/R6]
__device__ __forceinline__ void mma_bf16(float* c, const uint32_t* a, const uint32_t* b) {
    asm volatile(
        "mma.sync.aligned.m16n8k16.row.col.f32.bf16.bf16.f32 "
        "{%0,%1,%2,%3}, {%4,%5,%6,%7}, {%8,%9}, {%0,%1,%2,%3};"
        : "+f"(c[0]), "+f"(c[1]), "+f"(c[2]), "+f"(c[3])
        : "r"(a[0]), "r"(a[1]), "r"(a[2]), "r"(a[3]), "r"(b[0]), "r"(b[1]));
}

__device__ __forceinline__ void bf16_split(float v, __nv_bfloat16& hi, __nv_bfloat16& lo) {
    hi = __float2bfloat16(v);
    lo = __float2bfloat16(v - __bfloat162float(hi));
}

// ---------------- smem byte offsets for edge kernel (2 groups, 64-edge tiles) ----------------
#define SM_B1    0
#define SM_B2    512
#define SM_RC    1024
#define SM_II    1536
#define SM_JJ    2048
#define SM_W1HI  2560
#define SM_W1LO  12800
#define SM_WHI   23040
#define SM_WLO   57856
#define SM_FHI   92672
#define SM_FLO   102912
#define SM_HHI   113152
#define SM_HLO   147968
#define EDGE_SMEM_BYTES 182784

// ---------------- smem byte offsets for node gemm kernel ----------------
#define NSM_B    0
#define NSM_INHI 512
#define NSM_INLO 35328
#define NSM_WHI  70144
#define NSM_WLO  104960
#define NODE_SMEM_BYTES 139776

// ---------------- smem byte offsets for fused f2out kernel (2 groups, 64-row tiles) ----------------
#define N2_B1    0
#define N2_B2    512
#define N2_INHI  1024      // 2 x 17408
#define N2_INLO  35840     // 2 x 17408
#define N2_W1HI  70656
#define N2_W1LO  105472
#define N2_W2HI  140288
#define N2_W2LO  175104
#define NODE2_SMEM_BYTES 209920

// ---------------- prep kernels ----------------
__global__ void prep_zero() {
    if (threadIdx.x == 0) g_cnt = 0;
}

__global__ void edge_compact(const float* __restrict__ pos,
                             const int* __restrict__ idx_i,
                             const int* __restrict__ idx_j,
                             const int* __restrict__ edge_attr,
                             const float* __restrict__ edge_emb, int E) {
    int e = blockIdx.x * blockDim.x + threadIdx.x;
    int lane = threadIdx.x & 31;
    bool active = false;
    int a = 0, b = 0;
    float dd = 0.f;
    if (e < E) {
        a = idx_i[e]; b = idx_j[e];
        float dx = pos[a * 3 + 0] - pos[b * 3 + 0];
        float dy = pos[a * 3 + 1] - pos[b * 3 + 1];
        float dz = pos[a * 3 + 2] - pos[b * 3 + 2];
        dd = sqrtf(dx * dx + dy * dy + dz * dz);
        active = (dd < CUTOFF_F);
    }
    unsigned mask = __ballot_sync(0xffffffffu, active);
    if (!active) return;
    int leader = __ffs(mask) - 1;
    int rank = __popc(mask & ((1u << lane) - 1));
    int base = 0;
    if (lane == leader) base = atomicAdd(&g_cnt, __popc(mask));
    base = __shfl_sync(mask, base, leader);
    int p = base + rank;

    g_ci[p] = a;
    g_cj[p] = b;
    g_rc[p] = 0.5f * (__cosf(dd * (PI_F / CUTOFF_F)) + 1.0f);

    const float width = CUTOFF_F / 31.0f;
    const float coeff = -0.5f / (width * width);
    const float* emb = edge_emb + edge_attr[e] * NRBF;
    float4* dst = (float4*)(g_F + (size_t)p * NRBF);
#pragma unroll
    for (int j = 0; j < 8; j++) {
        float4 v;
        float u0 = dd - (float)(4 * j + 0) * width;
        float u1 = dd - (float)(4 * j + 1) * width;
        float u2 = dd - (float)(4 * j + 2) * width;
        float u3 = dd - (float)(4 * j + 3) * width;
        v.x = __expf(coeff * u0 * u0) + emb[4 * j + 0];
        v.y = __expf(coeff * u1 * u1) + emb[4 * j + 1];
        v.z = __expf(coeff * u2 * u2) + emb[4 * j + 2];
        v.w = __expf(coeff * u3 * u3) + emb[4 * j + 3];
        dst[j] = v;
    }
}

__global__ void embed_zero(const int* __restrict__ z, const int* __restrict__ z_res,
                           const float* __restrict__ ele_emb, const float* __restrict__ res_emb,
                           float* __restrict__ x, float* __restrict__ agg,
                           float* __restrict__ outbuf, int N, int out_n) {
    int t = blockIdx.x * blockDim.x + threadIdx.x;
    if (t < out_n) outbuf[t] = 0.f;
    if (t >= N * NB) return;
    int n = t >> 7, c = t & 127;
    agg[t] = 0.f;
    x[t] = ele_emb[z[n] * NB + c] + res_emb[z_res[n] * NB + c];
}

// ---------------- persistent HMMA node GEMM (1024 thr, R10/R16-proven) ----------------
// PRE: 0=none, 2=L2-normalize then silu
template <int PRE>
__global__ __launch_bounds__(1024, 1) void hmma_node_gemm(
    const float* __restrict__ in, const float* __restrict__ W,
    const float* __restrict__ bias,
    float* __restrict__ out, int M, int ntiles)
{
    extern __shared__ char smch[];
    float* sB = (float*)(smch + NSM_B);

    const int t = threadIdx.x;
    const int wid = t >> 5;
    const int lane = t & 31;
    const int q = lane & 3;
    const int lr = lane >> 2;

    if (t < 128) sB[t] = bias ? bias[t] : 0.f;
#pragma unroll
    for (int i = 0; i < 4; i++) {
        int idx4 = i * 1024 + t;
        int k = idx4 >> 5;
        int n0 = (idx4 & 31) * 4;
        float4 w = ((const float4*)W)[idx4];
        float vs[4] = { w.x, w.y, w.z, w.w };
#pragma unroll
        for (int d = 0; d < 4; d++) {
            __nv_bfloat16 hi, lo;
            bf16_split(vs[d], hi, lo);
            size_t off = ((size_t)(n0 + d) * 136 + k) * 2;
            *(__nv_bfloat16*)(smch + NSM_WHI + off) = hi;
            *(__nv_bfloat16*)(smch + NSM_WLO + off) = lo;
        }
    }
    __syncthreads();

    const int mg = wid & 3;
    const int ng = wid >> 2;

    for (int tile = blockIdx.x; tile < ntiles; tile += gridDim.x) {
        const int m0 = tile * 128;

        {
            int r = t >> 3, cq = (t & 7) * 16;
            const float4* src = (const float4*)(in + (size_t)(m0 + r) * NB + cq);
            bool ok = (m0 + r < M);
            float4 fv[4];
#pragma unroll
            for (int j = 0; j < 4; j++)
                fv[j] = ok ? src[j] : make_float4(0.f, 0.f, 0.f, 0.f);
            float scale = 1.0f;
            if (PRE == 2) {
                float ss = 0.f;
#pragma unroll
                for (int j = 0; j < 4; j++)
                    ss += fv[j].x * fv[j].x + fv[j].y * fv[j].y + fv[j].z * fv[j].z + fv[j].w * fv[j].w;
                ss += __shfl_xor_sync(0xffffffffu, ss, 1);
                ss += __shfl_xor_sync(0xffffffffu, ss, 2);
                ss += __shfl_xor_sync(0xffffffffu, ss, 4);
                scale = 1.0f / fmaxf(sqrtf(ss), 1e-12f);
            }
#pragma unroll
            for (int j = 0; j < 4; j++) {
                float4 f = fv[j];
                if (PRE == 2) {
                    f.x = siluf(f.x * scale); f.y = siluf(f.y * scale);
                    f.z = siluf(f.z * scale); f.w = siluf(f.w * scale);
                }
                __nv_bfloat162 h0, h1, l0, l1;
                bf16_split(f.x, h0.x, l0.x); bf16_split(f.y, h0.y, l0.y);
                bf16_split(f.z, h1.x, l1.x); bf16_split(f.w, h1.y, l1.y);
                size_t off = ((size_t)r * 136 + cq + j * 4) * 2;
                *(uint2*)(smch + NSM_INHI + off) = make_uint2(*(uint32_t*)&h0, *(uint32_t*)&h1);
                *(uint2*)(smch + NSM_INLO + off) = make_uint2(*(uint32_t*)&l0, *(uint32_t*)&l1);
            }
        }
        __syncthreads();

        float acc[2][2][4];
#pragma unroll
        for (int mt = 0; mt < 2; mt++)
#pragma unroll
            for (int nt = 0; nt < 2; nt++)
#pragma unroll
                for (int v = 0; v < 4; v++) acc[mt][nt][v] = 0.f;

#pragma unroll 2
        for (int ks = 0; ks < 8; ks++) {
            const int k0 = ks * 16;
            uint32_t ahi[2][4], alo[2][4];
#pragma unroll
            for (int mt = 0; mt < 2; mt++) {
                int m = mg * 32 + mt * 16 + lr;
                size_t o0 = ((size_t)m * 136 + k0 + 2 * q) * 2;
                size_t o1 = ((size_t)(m + 8) * 136 + k0 + 2 * q) * 2;
                ahi[mt][0] = *(const uint32_t*)(smch + NSM_INHI + o0);
                ahi[mt][1] = *(const uint32_t*)(smch + NSM_INHI + o1);
                ahi[mt][2] = *(const uint32_t*)(smch + NSM_INHI + o0 + 16);
                ahi[mt][3] = *(const uint32_t*)(smch + NSM_INHI + o1 + 16);
                alo[mt][0] = *(const uint32_t*)(smch + NSM_INLO + o0);
                alo[mt][1] = *(const uint32_t*)(smch + NSM_INLO + o1);
                alo[mt][2] = *(const uint32_t*)(smch + NSM_INLO + o0 + 16);
                alo[mt][3] = *(const uint32_t*)(smch + NSM_INLO + o1 + 16);
            }
#pragma unroll
            for (int nt = 0; nt < 2; nt++) {
                int n = ng * 16 + nt * 8 + lr;
                size_t ob = ((size_t)n * 136 + k0 + 2 * q) * 2;
                uint32_t bhi[2] = { *(const uint32_t*)(smch + NSM_WHI + ob),
                                    *(const uint32_t*)(smch + NSM_WHI + ob + 16) };
                uint32_t blo[2] = { *(const uint32_t*)(smch + NSM_WLO + ob),
                                    *(const uint32_t*)(smch + NSM_WLO + ob + 16) };
#pragma unroll
                for (int mt = 0; mt < 2; mt++) {
                    mma_bf16(acc[mt][nt], ahi[mt], bhi);
                    mma_bf16(acc[mt][nt], ahi[mt], blo);
                    mma_bf16(acc[mt][nt], alo[mt], bhi);
                }
            }
        }

#pragma unroll
        for (int mt = 0; mt < 2; mt++) {
#pragma unroll
            for (int half = 0; half < 2; half++) {
                int rr = mg * 32 + mt * 16 + lr + 8 * half;
                int m = m0 + rr;
                if (m < M) {
                    float* orow = out + (size_t)m * NB;
#pragma unroll
                    for (int nt = 0; nt < 2; nt++) {
                        int c = ng * 16 + nt * 8 + 2 * q;
                        float2 bv = *(const float2*)&sB[c];
                        *(float2*)(orow + c) = make_float2(acc[mt][nt][2 * half] + bv.x,
                                                           acc[mt][nt][2 * half + 1] + bv.y);
                    }
                }
            }
        }
        __syncthreads();
    }
}

// ---------------- fused f2out: 2 independent 256-thr groups, 64-row tiles ----------------
// x += ssp(agg@W1+b1)@W2+b2 ; zero agg
__global__ __launch_bounds__(512, 1) void hmma_f2out(
    const float* __restrict__ agg_in, const float* __restrict__ W1,
    const float* __restrict__ b1, const float* __restrict__ W2,
    const float* __restrict__ b2, float* __restrict__ x,
    float* __restrict__ aggz, int M, int ntiles)
{
    extern __shared__ char smch[];
    float* sB1 = (float*)(smch + N2_B1);
    float* sB2 = (float*)(smch + N2_B2);

    const int t = threadIdx.x;
    const int wid = t >> 5;
    const int lane = t & 31;
    const int q = lane & 3;
    const int lr = lane >> 2;

    const int grp = wid >> 3;
    const int gwid = wid & 7;
    const int tg = t & 255;
    const int barid = grp + 1;

    char* sINHI = smch + N2_INHI + grp * 17408;
    char* sINLO = smch + N2_INLO + grp * 17408;

    if (t < 128) { sB1[t] = b1[t]; sB2[t] = b2[t]; }
#pragma unroll
    for (int i = 0; i < 8; i++) {
        int idx4 = i * 512 + t;
        int k = idx4 >> 5;
        int n0 = (idx4 & 31) * 4;
        float4 w1 = ((const float4*)W1)[idx4];
        float4 w2 = ((const float4*)W2)[idx4];
        float v1[4] = { w1.x, w1.y, w1.z, w1.w };
        float v2[4] = { w2.x, w2.y, w2.z, w2.w };
#pragma unroll
        for (int d = 0; d < 4; d++) {
            size_t off = ((size_t)(n0 + d) * 136 + k) * 2;
            __nv_bfloat16 hi, lo;
            bf16_split(v1[d], hi, lo);
            *(__nv_bfloat16*)(smch + N2_W1HI + off) = hi;
            *(__nv_bfloat16*)(smch + N2_W1LO + off) = lo;
            bf16_split(v2[d], hi, lo);
            *(__nv_bfloat16*)(smch + N2_W2HI + off) = hi;
            *(__nv_bfloat16*)(smch + N2_W2LO + off) = lo;
        }
    }
    __syncthreads();

    // group warp tiling: mg rows(32) in {0,1}, ng cols(32) in {0..3}
    const int mg = gwid & 1;
    const int ng = gwid >> 1;

    for (int tile = blockIdx.x * 2 + grp; tile < ntiles; tile += gridDim.x * 2) {
        const int m0 = tile * 64;

        // stage agg tile (64 rows): thread tg -> row tg>>2, cols (tg&3)*32
        {
            int r = tg >> 2, cq = (tg & 3) * 32;
            const float4* src = (const float4*)(agg_in + (size_t)(m0 + r) * NB + cq);
            bool ok = (m0 + r < M);
#pragma unroll
            for (int j = 0; j < 8; j++) {
                float4 f = ok ? src[j] : make_float4(0.f, 0.f, 0.f, 0.f);
                __nv_bfloat162 h0, h1, l0, l1;
                bf16_split(f.x, h0.x, l0.x); bf16_split(f.y, h0.y, l0.y);
                bf16_split(f.z, h1.x, l1.x); bf16_split(f.w, h1.y, l1.y);
                size_t off = ((size_t)r * 136 + cq + j * 4) * 2;
                *(uint2*)(sINHI + off) = make_uint2(*(uint32_t*)&h0, *(uint32_t*)&h1);
                *(uint2*)(sINLO + off) = make_uint2(*(uint32_t*)&l0, *(uint32_t*)&l1);
            }
        }
        bar_grp(barid);

        float acc[2][4][4];
#pragma unroll
        for (int mt = 0; mt < 2; mt++)
#pragma unroll
            for (int nt = 0; nt < 4; nt++)
#pragma unroll
                for (int v = 0; v < 4; v++) acc[mt][nt][v] = 0.f;

        // phase 1: C1 = agg @ W1
#pragma unroll 2
        for (int ks = 0; ks < 8; ks++) {
            const int k0 = ks * 16;
            uint32_t ahi[2][4], alo[2][4];
#pragma unroll
            for (int mt = 0; mt < 2; mt++) {
                int m = mg * 32 + mt * 16 + lr;
                size_t o0 = ((size_t)m * 136 + k0 + 2 * q) * 2;
                size_t o1 = ((size_t)(m + 8) * 136 + k0 + 2 * q) * 2;
                ahi[mt][0] = *(const uint32_t*)(sINHI + o0);
                ahi[mt][1] = *(const uint32_t*)(sINHI + o1);
                ahi[mt][2] = *(const uint32_t*)(sINHI + o0 + 16);
                ahi[mt][3] = *(const uint32_t*)(sINHI + o1 + 16);
                alo[mt][0] = *(const uint32_t*)(sINLO + o0);
                alo[mt][1] = *(const uint32_t*)(sINLO + o1);
                alo[mt][2] = *(const uint32_t*)(sINLO + o0 + 16);
                alo[mt][3] = *(const uint32_t*)(sINLO + o1 + 16);
            }
#pragma unroll
            for (int nt = 0; nt < 4; nt++) {
                int n = ng * 32 + nt * 8 + lr;
                size_t ob = ((size_t)n * 136 + k0 + 2 * q) * 2;
                uint32_t bhi[2] = { *(const uint32_t*)(smch + N2_W1HI + ob),
                                    *(const uint32_t*)(smch + N2_W1HI + ob + 16) };
                uint32_t blo[2] = { *(const uint32_t*)(smch + N2_W1LO + ob),
                                    *(const uint32_t*)(smch + N2_W1LO + ob + 16) };
#pragma unroll
                for (int mt = 0; mt < 2; mt++) {
                    mma_bf16(acc[mt][nt], ahi[mt], bhi);
                    mma_bf16(acc[mt][nt], ahi[mt], blo);
                    mma_bf16(acc[mt][nt], alo[mt], bhi);
                }
            }
        }
        bar_grp(barid);  // all phase-1 reads of IN done

        // H = ssp(C1 + b1) -> overwrite IN buffers
#pragma unroll
        for (int mt = 0; mt < 2; mt++) {
#pragma unroll
            for (int half = 0; half < 2; half++) {
                int rr = mg * 32 + mt * 16 + lr + 8 * half;
#pragma unroll
                for (int nt = 0; nt < 4; nt++) {
                    int c = ng * 32 + nt * 8 + 2 * q;
                    float2 bv = *(const float2*)&sB1[c];
                    float h0 = sspf(acc[mt][nt][2 * half] + bv.x);
                    float h1 = sspf(acc[mt][nt][2 * half + 1] + bv.y);
                    __nv_bfloat162 hh, ll;
                    bf16_split(h0, hh.x, ll.x);
                    bf16_split(h1, hh.y, ll.y);
                    size_t off = ((size_t)rr * 136 + c) * 2;
                    *(uint32_t*)(sINHI + off) = *(uint32_t*)&hh;
                    *(uint32_t*)(sINLO + off) = *(uint32_t*)&ll;
                }
            }
        }
        bar_grp(barid);

        // phase 2: C2 = H @ W2
#pragma unroll
        for (int mt = 0; mt < 2; mt++)
#pragma unroll
            for (int nt = 0; nt < 4; nt++)
#pragma unroll
                for (int v = 0; v < 4; v++) acc[mt][nt][v] = 0.f;

#pragma unroll 2
        for (int ks = 0; ks < 8; ks++) {
            const int k0 = ks * 16;
            uint32_t ahi[2][4], alo[2][4];
#pragma unroll
            for (int mt = 0; mt < 2; mt++) {
                int m = mg * 32 + mt * 16 + lr;
                size_t o0 = ((size_t)m * 136 + k0 + 2 * q) * 2;
                size_t o1 = ((size_t)(m + 8) * 136 + k0 + 2 * q) * 2;
                ahi[mt][0] = *(const uint32_t*)(sINHI + o0);
                ahi[mt][1] = *(const uint32_t*)(sINHI + o1);
                ahi[mt][2] = *(const uint32_t*)(sINHI + o0 + 16);
                ahi[mt][3] = *(const uint32_t*)(sINHI + o1 + 16);
                alo[mt][0] = *(const uint32_t*)(sINLO + o0);
                alo[mt][1] = *(const uint32_t*)(sINLO + o1);
                alo[mt][2] = *(const uint32_t*)(sINLO + o0 + 16);
                alo[mt][3] = *(const uint32_t*)(sINLO + o1 + 16);
            }
#pragma unroll
            for (int nt = 0; nt < 4; nt++) {
                int n = ng * 32 + nt * 8 + lr;
                size_t ob = ((size_t)n * 136 + k0 + 2 * q) * 2;
                uint32_t bhi[2] = { *(const uint32_t*)(smch + N2_W2HI + ob),
                                    *(const uint32_t*)(smch + N2_W2HI + ob + 16) };
                uint32_t blo[2] = { *(const uint32_t*)(smch + N2_W2LO + ob),
                                    *(const uint32_t*)(smch + N2_W2LO + ob + 16) };
#pragma unroll
                for (int mt = 0; mt < 2; mt++) {
                    mma_bf16(acc[mt][nt], ahi[mt], bhi);
                    mma_bf16(acc[mt][nt], ahi[mt], blo);
                    mma_bf16(acc[mt][nt], alo[mt], bhi);
                }
            }
        }

        // epilogue: x += C2 + b2 ; zero agg
#pragma unroll
        for (int mt = 0; mt < 2; mt++) {
#pragma unroll
            for (int half = 0; half < 2; half++) {
                int rr = mg * 32 + mt * 16 + lr + 8 * half;
                int m = m0 + rr;
                if (m < M) {
                    float* xrow = x + (size_t)m * NB;
                    float* zrow = aggz ? aggz + (size_t)m * NB : 0;
#pragma unroll
                    for (int nt = 0; nt < 4; nt++) {
                        int c = ng * 32 + nt * 8 + 2 * q;
                        float2 bv = *(const float2*)&sB2[c];
                        float2 xv = *(const float2*)(xrow + c);
                        *(float2*)(xrow + c) = make_float2(xv.x + acc[mt][nt][2 * half] + bv.x,
                                                           xv.y + acc[mt][nt][2 * half + 1] + bv.y);
                        if (aggz) *(float2*)(zrow + c) = make_float2(0.f, 0.f);
                    }
                }
            }
        }
        bar_grp(barid);
    }
}

// ---------------- persistent fused edge kernel: 2 independent 256-thr groups (R16-proven) ----------------
__global__ __launch_bounds__(512, 1) void edge_kernel(
    const int* __restrict__ ci, const int* __restrict__ cj,
    const float* __restrict__ W1, const float* __restrict__ b1,
    const float* __restrict__ W2, const float* __restrict__ b2,
    const float* __restrict__ Ff, const float* __restrict__ rcut,
    const float* __restrict__ xf, float* __restrict__ agg,
    const int* __restrict__ cntPtr)
{
    extern __shared__ char smch[];
    float* sB1 = (float*)(smch + SM_B1);
    float* sB2 = (float*)(smch + SM_B2);

    const int E = *cntPtr;
    const int ntiles = (E + 63) >> 6;

    const int t = threadIdx.x;
    const int wid = t >> 5;
    const int lane = t & 31;
    const int q = lane & 3;
    const int lr = lane >> 2;

    const int grp = wid >> 3;
    const int gwid = wid & 7;
    const int tg = t & 255;
    const int barid = grp + 1;

    float* sRC = (float*)(smch + SM_RC + grp * 256);
    int*   sII = (int*)(smch + SM_II + grp * 256);
    int*   sJJ = (int*)(smch + SM_JJ + grp * 256);
    char*  sFHI = smch + SM_FHI + grp * 5120;
    char*  sFLO = smch + SM_FLO + grp * 5120;
    char*  sHHI = smch + SM_HHI + grp * 17408;
    char*  sHLO = smch + SM_HLO + grp * 17408;

    if (t < 128) { sB1[t] = b1[t]; sB2[t] = b2[t]; }
#pragma unroll
    for (int i = 0; i < 2; i++) {
        int idx4 = i * 512 + t;
        int k = idx4 >> 5;
        int n0 = (idx4 & 31) * 4;
        float4 w = ((const float4*)W1)[idx4];
        float vs[4] = { w.x, w.y, w.z, w.w };
#pragma unroll
        for (int d = 0; d < 4; d++) {
            __nv_bfloat16 hi, lo;
            bf16_split(vs[d], hi, lo);
            size_t off = ((size_t)(n0 + d) * 40 + k) * 2;
            *(__nv_bfloat16*)(smch + SM_W1HI + off) = hi;
            *(__nv_bfloat16*)(smch + SM_W1LO + off) = lo;
        }
    }
#pragma unroll
    for (int i = 0; i < 8; i++) {
        int idx4 = i * 512 + t;
        int k = idx4 >> 5;
        int n0 = (idx4 & 31) * 4;
        float4 w = ((const float4*)W2)[idx4];
        float vs[4] = { w.x, w.y, w.z, w.w };
#pragma unroll
        for (int d = 0; d < 4; d++) {
            __nv_bfloat16 hi, lo;
            bf16_split(vs[d], hi, lo);
            size_t off = ((size_t)(n0 + d) * 136 + k) * 2;
            *(__nv_bfloat16*)(smch + SM_WHI + off) = hi;
            *(__nv_bfloat16*)(smch + SM_WLO + off) = lo;
        }
    }
    __syncthreads();

    const int pm = gwid & 3;
    const int pn = gwid >> 2;
    const int mg = gwid & 1;
    const int ng = gwid >> 1;

    for (int tile = blockIdx.x * 2 + grp; tile < ntiles; tile += gridDim.x * 2) {
        const int eb = tile * 64;

        {
            int r = tg >> 2, kq = (tg & 3) * 8;
            float4 f0 = make_float4(0.f, 0.f, 0.f, 0.f);
            float4 f1 = make_float4(0.f, 0.f, 0.f, 0.f);
            if (eb + r < E) {
                const float4* src = (const float4*)(Ff + (size_t)(eb + r) * NRBF + kq);
                f0 = src[0]; f1 = src[1];
            }
            __nv_bfloat162 h0, h1, h2, h3, l0, l1, l2, l3;
            bf16_split(f0.x, h0.x, l0.x); bf16_split(f0.y, h0.y, l0.y);
            bf16_split(f0.z, h1.x, l1.x); bf16_split(f0.w, h1.y, l1.y);
            bf16_split(f1.x, h2.x, l2.x); bf16_split(f1.y, h2.y, l2.y);
            bf16_split(f1.z, h3.x, l3.x); bf16_split(f1.w, h3.y, l3.y);
            size_t off = ((size_t)r * 40 + kq) * 2;
            uint4 uh = make_uint4(*(uint32_t*)&h0, *(uint32_t*)&h1, *(uint32_t*)&h2, *(uint32_t*)&h3);
            uint4 ul = make_uint4(*(uint32_t*)&l0, *(uint32_t*)&l1, *(uint32_t*)&l2, *(uint32_t*)&l3);
            *(uint4*)(sFHI + off) = uh;
            *(uint4*)(sFLO + off) = ul;
        }
        if (tg < 64) {
            int e = eb + tg;
            float rcv = 0.f; int iiv = 0, jjv = 0;
            if (e < E) { rcv = rcut[e]; iiv = ci[e]; jjv = cj[e]; }
            sRC[tg] = rcv; sII[tg] = iiv; sJJ[tg] = jjv;
        }
        bar_grp(barid);

        {
            const int m0 = pm * 16, n0 = pn * 64;
            uint32_t ahi[2][4], alo[2][4];
#pragma unroll
            for (int ks = 0; ks < 2; ks++) {
                size_t o0 = ((size_t)(m0 + lr) * 40 + ks * 16 + 2 * q) * 2;
                size_t o1 = o0 + 640;
                ahi[ks][0] = *(const uint32_t*)(sFHI + o0);
                ahi[ks][1] = *(const uint32_t*)(sFHI + o1);
                ahi[ks][2] = *(const uint32_t*)(sFHI + o0 + 16);
                ahi[ks][3] = *(const uint32_t*)(sFHI + o1 + 16);
                alo[ks][0] = *(const uint32_t*)(sFLO + o0);
                alo[ks][1] = *(const uint32_t*)(sFLO + o1);
                alo[ks][2] = *(const uint32_t*)(sFLO + o0 + 16);
                alo[ks][3] = *(const uint32_t*)(sFLO + o1 + 16);
            }
#pragma unroll
            for (int nt = 0; nt < 8; nt++) {
                int n = n0 + nt * 8 + lr;
                float c[4] = { 0.f, 0.f, 0.f, 0.f };
#pragma unroll
                for (int ks = 0; ks < 2; ks++) {
                    size_t ob = ((size_t)n * 40 + ks * 16 + 2 * q) * 2;
                    uint32_t bh[2] = { *(const uint32_t*)(smch + SM_W1HI + ob),
                                       *(const uint32_t*)(smch + SM_W1HI + ob + 16) };
                    uint32_t bl[2] = { *(const uint32_t*)(smch + SM_W1LO + ob),
                                       *(const uint32_t*)(smch + SM_W1LO + ob + 16) };
                    mma_bf16(c, ahi[ks], bh);
                    mma_bf16(c, ahi[ks], bl);
                    mma_bf16(c, alo[ks], bh);
                }
                int cc = n0 + nt * 8 + 2 * q;
                float2 bv = *(const float2*)&sB1[cc];
                float h00 = sspf(c[0] + bv.x), h01 = sspf(c[1] + bv.y);
                float h10 = sspf(c[2] + bv.x), h11 = sspf(c[3] + bv.y);
                __nv_bfloat162 p0, p1, e0, e1;
                bf16_split(h00, p0.x, e0.x); bf16_split(h01, p0.y, e0.y);
                bf16_split(h10, p1.x, e1.x); bf16_split(h11, p1.y, e1.y);
                size_t oh0 = ((size_t)(m0 + lr) * 136 + cc) * 2;
                size_t oh1 = oh0 + 136 * 8 * 2;
                *(uint32_t*)(sHHI + oh0) = *(uint32_t*)&p0;
                *(uint32_t*)(sHHI + oh1) = *(uint32_t*)&p1;
                *(uint32_t*)(sHLO + oh0) = *(uint32_t*)&e0;
                *(uint32_t*)(sHLO + oh1) = *(uint32_t*)&e1;
            }
        }
        bar_grp(barid);

        {
            float acc[2][4][4];
#pragma unroll
            for (int mt = 0; mt < 2; mt++)
#pragma unroll
                for (int nt = 0; nt < 4; nt++)
#pragma unroll
                    for (int v = 0; v < 4; v++) acc[mt][nt][v] = 0.f;

#pragma unroll 2
            for (int ks = 0; ks < 8; ks++) {
                const int k0 = ks * 16;
                uint32_t ahi[2][4], alo[2][4];
#pragma unroll
                for (int mt = 0; mt < 2; mt++) {
                    int m = mg * 32 + mt * 16 + lr;
                    size_t o0 = ((size_t)m * 136 + k0 + 2 * q) * 2;
                    size_t o1 = ((size_t)(m + 8) * 136 + k0 + 2 * q) * 2;
                    ahi[mt][0] = *(const uint32_t*)(sHHI + o0);
                    ahi[mt][1] = *(const uint32_t*)(sHHI + o1);
                    ahi[mt][2] = *(const uint32_t*)(sHHI + o0 + 16);
                    ahi[mt][3] = *(const uint32_t*)(sHHI + o1 + 16);
                    alo[mt][0] = *(const uint32_t*)(sHLO + o0);
                    alo[mt][1] = *(const uint32_t*)(sHLO + o1);
                    alo[mt][2] = *(const uint32_t*)(sHLO + o0 + 16);
                    alo[mt][3] = *(const uint32_t*)(sHLO + o1 + 16);
                }
#pragma unroll
                for (int nt = 0; nt < 4; nt++) {
                    int n = ng * 32 + nt * 8 + lr;
                    size_t ob = ((size_t)n * 136 + k0 + 2 * q) * 2;
                    uint32_t bhi[2] = { *(const uint32_t*)(smch + SM_WHI + ob),
                                        *(const uint32_t*)(smch + SM_WHI + ob + 16) };
                    uint32_t blo[2] = { *(const uint32_t*)(smch + SM_WLO + ob),
                                        *(const uint32_t*)(smch + SM_WLO + ob + 16) };
#pragma unroll
                    for (int mt = 0; mt < 2; mt++) {
                        mma_bf16(acc[mt][nt], ahi[mt], bhi);
                        mma_bf16(acc[mt][nt], ahi[mt], blo);
                        mma_bf16(acc[mt][nt], alo[mt], bhi);
                    }
                }
            }

#pragma unroll
            for (int mt = 0; mt < 2; mt++) {
#pragma unroll
                for (int half = 0; half < 2; half++) {
                    int r = mg * 32 + mt * 16 + lr + 8 * half;
                    float rc = sRC[r];
                    int ii = sII[r], jj = sJJ[r];
                    const float* xrow = xf + (size_t)jj * NB;
                    float* arow = agg + (size_t)ii * NB;
#pragma unroll
                    for (int nt = 0; nt < 4; nt++) {
                        int c = ng * 32 + nt * 8 + 2 * q;
                        float2 xv = *(const float2*)(xrow + c);
                        float2 bv = *(const float2*)&sB2[c];
                        float v0 = (acc[mt][nt][2 * half]     + bv.x) * rc * xv.x;
                        float v1 = (acc[mt][nt][2 * half + 1] + bv.y) * rc * xv.y;
                        red_add_v2(arow + c, v0, v1);
                    }
                }
            }
        }
        bar_grp(barid);
    }
}

// ---------------- head ----------------
__global__ void head_final(const float* __restrict__ h, const float* __restrict__ w2,
                           const int* __restrict__ batch, float* __restrict__ out, int M) {
    int w = (blockIdx.x * blockDim.x + threadIdx.x) >> 5;
    int lane = threadIdx.x & 31;
    if (w >= M) return;
    float4 v = ((const float4*)(h + (size_t)w * NB))[lane];
    float4 ww = ((const float4*)w2)[lane];
    float s = siluf(v.x) * ww.x + siluf(v.y) * ww.y + siluf(v.z) * ww.z + siluf(v.w) * ww.w;
#pragma unroll
    for (int o2 = 16; o2 > 0; o2 >>= 1) s += __shfl_xor_sync(0xffffffffu, s, o2);
    if (lane == 0) atomicAdd(&out[batch[w]], s);
}

// ---------------- launch ----------------
typedef void (*ngemm_fn)(const float*, const float*, const float*, float*, int, int);

extern "C" void kernel_launch(void* const* d_in, const int* in_sizes, int n_in,
                              void* d_out, int out_size)
{
    const int*   z         = (const int*)d_in[0];
    const int*   z_res     = (const int*)d_in[1];
    const float* pos       = (const float*)d_in[2];
    const int*   idx_i     = (const int*)d_in[3];
    const int*   idx_j     = (const int*)d_in[4];
    const int*   edge_attr = (const int*)d_in[5];
    const int*   batch     = (const int*)d_in[6];
    const float* ele_emb   = (const float*)d_in[7];
    const float* res_emb   = (const float*)d_in[8];
    const float* edge_emb  = (const float*)d_in[9];
    const float* in2f_W    = (const float*)d_in[10];
    const float* filt_W1   = (const float*)d_in[11];
    const float* filt_b1   = (const float*)d_in[12];
    const float* filt_W2   = (const float*)d_in[13];
    const float* filt_b2   = (const float*)d_in[14];
    const float* f2out_W1  = (const float*)d_in[15];
    const float* f2out_b1  = (const float*)d_in[16];
    const float* f2out_W2  = (const float*)d_in[17];
    const float* f2out_b2  = (const float*)d_in[18];
    const float* head_W1   = (const float*)d_in[19];
    const float* head_b1   = (const float*)d_in[20];
    const float* head_W2   = (const float*)d_in[21];
    float* out = (float*)d_out;

    const int N = in_sizes[0];
    const int E = in_sizes[3];

    int *pCnt, *pCi, *pCj;
    float *pRc, *pF, *pX, *pXf, *pAgg;
    cudaGetSymbolAddress((void**)&pCnt, g_cnt);
    cudaGetSymbolAddress((void**)&pCi, g_ci);
    cudaGetSymbolAddress((void**)&pCj, g_cj);
    cudaGetSymbolAddress((void**)&pRc, g_rc);
    cudaGetSymbolAddress((void**)&pF, g_F);
    cudaGetSymbolAddress((void**)&pX, g_x);
    cudaGetSymbolAddress((void**)&pXf, g_xf);
    cudaGetSymbolAddress((void**)&pAgg, g_agg);

    ngemm_fn f_plain = hmma_node_gemm<0>;
    ngemm_fn f_head  = hmma_node_gemm<2>;

    cudaFuncSetAttribute((const void*)f_plain, cudaFuncAttributeMaxDynamicSharedMemorySize, NODE_SMEM_BYTES);
    cudaFuncSetAttribute((const void*)f_head,  cudaFuncAttributeMaxDynamicSharedMemorySize, NODE_SMEM_BYTES);
    cudaFuncSetAttribute((const void*)hmma_f2out, cudaFuncAttributeMaxDynamicSharedMemorySize, NODE2_SMEM_BYTES);
    cudaFuncSetAttribute((const void*)edge_kernel, cudaFuncAttributeMaxDynamicSharedMemorySize, EDGE_SMEM_BYTES);

    int nsm = 148;
    cudaDeviceGetAttribute(&nsm, cudaDevAttrMultiProcessorCount, 0);
    const int ntiles = (N + 127) / 128;
    const int n64tiles = (N + 63) / 64;

    prep_zero<<<1, 32>>>();
    edge_compact<<<(E + 255) / 256, 256>>>(pos, idx_i, idx_j, edge_attr, edge_emb, E);
    embed_zero<<<(N * NB + 255) / 256, 256>>>(z, z_res, ele_emb, res_emb, pX, pAgg, out, N, out_size);

    for (int it = 0; it < 6; it++) {
        f_plain<<<nsm, 1024, NODE_SMEM_BYTES>>>(
            pX, in2f_W + (size_t)it * NB * NB, nullptr, pXf, N, ntiles);
        edge_kernel<<<nsm, 512, EDGE_SMEM_BYTES>>>(
            pCi, pCj,
            filt_W1 + (size_t)it * NRBF * NB, filt_b1 + (size_t)it * NB,
            filt_W2 + (size_t)it * NB * NB,  filt_b2 + (size_t)it * NB,
            pF, pRc, pXf, pAgg, pCnt);
        hmma_f2out<<<nsm, 512, NODE2_SMEM_BYTES>>>(
            pAgg, f2out_W1 + (size_t)it * NB * NB, f2out_b1 + (size_t)it * NB,
            f2out_W2 + (size_t)it * NB * NB, f2out_b2 + (size_t)it * NB,
            pX, (it < 5) ? pAgg : nullptr, N, n64tiles);
    }

    f_head<<<nsm, 1024, NODE_SMEM_BYTES>>>(pX, head_W1, head_b1, pXf, N, n64tiles * 0 + ntiles);
    head_final<<<(N + 7) / 8, 256>>>(pXf, head_W2, batch, out, N);
}